// round 5
// baseline (speedup 1.0000x reference)
#include <cuda_runtime.h>
#include <math.h>
#include <stdint.h>

// ---------------------------------------------------------------------------
// Problem constants
// ---------------------------------------------------------------------------
#define BB 2
#define LL 4096
#define DMOD 1024
#define DI 2048
#define DTR 64
#define KC 4
#define ROWS (BB * LL)       // 8192
#define NCH 64               // scan chunks
#define LC (LL / NCH)        // 64

// ---------------------------------------------------------------------------
// Scratch (device globals; no allocation allowed)
// ---------------------------------------------------------------------------
__device__ float g_xz[(size_t)ROWS * 2 * DI];
__device__ float g_u [(size_t)ROWS * DI];
__device__ float g_dtlow[(size_t)ROWS * DTR];
__device__ float g_e [(size_t)ROWS * DI];
__device__ float g_yg[(size_t)ROWS * DI];
__device__ float g_S [(size_t)BB * NCH * DI];
__device__ float g_P [(size_t)BB * NCH * DI];
__device__ float g_C [(size_t)BB * NCH * DI];
__device__ float g_xr  [(size_t)ROWS * DMOD];
__device__ float g_inwr[(size_t)2 * DI * DMOD];
__device__ float g_outwr[(size_t)DMOD * DI];
__device__ float g_xpwr[(size_t)DTR * DI];
__device__ float g_dtwr[(size_t)DI * DTR];

// ---------------------------------------------------------------------------
// PTX helpers (generic ISA: cp.async + mma.sync tf32 — sm_103-safe)
// ---------------------------------------------------------------------------
__device__ __forceinline__ uint32_t smem_u32(const void* p) {
    uint32_t a;
    asm("{ .reg .u64 t; cvta.to.shared.u64 t, %1; cvt.u32.u64 %0, t; }"
        : "=r"(a) : "l"(p));
    return a;
}
__device__ __forceinline__ void cp_async16(uint32_t dst, const void* src) {
    asm volatile("cp.async.cg.shared.global [%0], [%1], 16;"
                 :: "r"(dst), "l"(src) : "memory");
}
#define CP_COMMIT() asm volatile("cp.async.commit_group;" ::: "memory")
#define CP_WAIT(n)  asm volatile("cp.async.wait_group %0;" :: "n"(n) : "memory")

__device__ __forceinline__ uint32_t f2tf32(float f) {
    uint32_t r;
    asm("cvt.rna.tf32.f32 %0, %1;" : "=r"(r) : "f"(f));
    return r;
}
__device__ __forceinline__ void mma_tf32(float* c, const uint32_t* a, const uint32_t* b) {
    asm volatile(
        "mma.sync.aligned.m16n8k8.row.col.f32.tf32.tf32.f32 "
        "{%0,%1,%2,%3}, {%4,%5,%6,%7}, {%8,%9}, {%0,%1,%2,%3};"
        : "+f"(c[0]), "+f"(c[1]), "+f"(c[2]), "+f"(c[3])
        : "r"(a[0]), "r"(a[1]), "r"(a[2]), "r"(a[3]), "r"(b[0]), "r"(b[1]));
}

__device__ __forceinline__ float e_from_dpre(float acc, float bias, float al) {
    float v = acc + bias;
    float delta = (v > 20.f) ? v : log1pf(expf(v));
    delta = fminf(fmaxf(delta, 1e-6f), 10.f);
    float A = fminf(fmaxf(-expf(al), -10.f), -1e-6f);
    float ev = expf(delta * A);
    return fminf(fmaxf(ev, 1e-6f), 1.f);
}

#define GBK 32
#define SST 40

// ---------------------------------------------------------------------------
// Big GEMM: C[M,N] = A[M,K]*B[N,K]^T. BM=128, BN=256, 512 threads (16 warps,
// 2x8 warp grid, warp tile 64x32, MT=4 NT=4). BK=32, cp.async double buffer.
// SST=40 -> conflict-free LDS.64 fragment loads (paired k-slots (q, q+4)
// on both operands; contraction symmetric over k).
// EPI: 0=plain store, 2=fused softplus/exp e-epilogue (vb1=dtb, vb2=A_log).
// ---------------------------------------------------------------------------
template <int EPI>
__global__ __launch_bounds__(512, 1)
void gemm_big(const float* __restrict__ A, const float* __restrict__ B,
              float* __restrict__ C, int M, int N, int K,
              const float* __restrict__ vb1, const float* __restrict__ vb2) {
    constexpr int BM = 128, BN = 256;
    constexpr int MT = 4, NT = 4;
    constexpr int AF4 = (BM * 8) / 512;   // 2
    constexpr int BF4 = (BN * 8) / 512;   // 4

    extern __shared__ float smem[];
    float* As = smem;                    // [2][BM*SST]
    float* Bs = smem + 2 * BM * SST;     // [2][BN*SST]

    const int tid = threadIdx.x;
    const int wid = tid >> 5;
    const int lane = tid & 31;
    const int grp = lane >> 2;
    const int qid = lane & 3;
    const int wm = wid >> 3;      // 0..1
    const int wn = wid & 7;       // 0..7

    const int bx = blockIdx.x, by = blockIdx.y;
    const float* Ag = A + (size_t)by * BM * K;
    const float* Bg = B + (size_t)bx * BN * K;

    const uint32_t sA = smem_u32(As);
    const uint32_t sB = smem_u32(Bs);

    float acc[MT][NT][4];
    #pragma unroll
    for (int i = 0; i < MT; i++)
        #pragma unroll
        for (int j = 0; j < NT; j++)
            #pragma unroll
            for (int q = 0; q < 4; q++) acc[i][j][q] = 0.f;

    const int nK = K / GBK;

    #pragma unroll
    for (int t = 0; t < AF4; t++) {
        int f4 = tid + t * 512;
        int row = f4 >> 3, c4 = f4 & 7;
        cp_async16(sA + (row * SST + c4 * 4) * 4, Ag + (size_t)row * K + c4 * 4);
    }
    #pragma unroll
    for (int t = 0; t < BF4; t++) {
        int f4 = tid + t * 512;
        int row = f4 >> 3, c4 = f4 & 7;
        cp_async16(sB + (row * SST + c4 * 4) * 4, Bg + (size_t)row * K + c4 * 4);
    }
    CP_COMMIT();

    int buf = 0;
    for (int kt = 0; kt < nK; kt++) {
        if (kt + 1 < nK) {
            const uint32_t dA = sA + (buf ^ 1) * BM * SST * 4;
            const uint32_t dB = sB + (buf ^ 1) * BN * SST * 4;
            const int koff = (kt + 1) * GBK;
            #pragma unroll
            for (int t = 0; t < AF4; t++) {
                int f4 = tid + t * 512;
                int row = f4 >> 3, c4 = f4 & 7;
                cp_async16(dA + (row * SST + c4 * 4) * 4, Ag + (size_t)row * K + koff + c4 * 4);
            }
            #pragma unroll
            for (int t = 0; t < BF4; t++) {
                int f4 = tid + t * 512;
                int row = f4 >> 3, c4 = f4 & 7;
                cp_async16(dB + (row * SST + c4 * 4) * 4, Bg + (size_t)row * K + koff + c4 * 4);
            }
            CP_COMMIT();
            CP_WAIT(1);
        } else {
            CP_WAIT(0);
        }
        __syncthreads();

        const float* Ab = As + buf * BM * SST;
        const float* Bb = Bs + buf * BN * SST;

        #pragma unroll
        for (int s = 0; s < GBK / 8; s++) {
            const int kc2 = s * 8 + 2 * qid;
            uint32_t af[MT][4];
            #pragma unroll
            for (int mt = 0; mt < MT; mt++) {
                const int r0 = wm * 64 + mt * 16 + grp;
                float2 v0 = *(const float2*)(Ab + r0 * SST + kc2);
                float2 v1 = *(const float2*)(Ab + (r0 + 8) * SST + kc2);
                af[mt][0] = __float_as_uint(v0.x); af[mt][2] = __float_as_uint(v0.y);
                af[mt][1] = __float_as_uint(v1.x); af[mt][3] = __float_as_uint(v1.y);
            }
            uint32_t bf[NT][2];
            #pragma unroll
            for (int nt = 0; nt < NT; nt++) {
                const int c0 = wn * 32 + nt * 8 + grp;
                float2 v = *(const float2*)(Bb + c0 * SST + kc2);
                bf[nt][0] = __float_as_uint(v.x);
                bf[nt][1] = __float_as_uint(v.y);
            }
            #pragma unroll
            for (int mt = 0; mt < MT; mt++)
                #pragma unroll
                for (int nt = 0; nt < NT; nt++)
                    mma_tf32(acc[mt][nt], af[mt], bf[nt]);
        }
        __syncthreads();
        buf ^= 1;
    }

    #pragma unroll
    for (int mt = 0; mt < MT; mt++) {
        const int r0 = by * BM + wm * 64 + mt * 16 + grp;
        #pragma unroll
        for (int nt = 0; nt < NT; nt++) {
            const int c0 = bx * BN + wn * 32 + nt * 8 + qid * 2;
            float o0 = acc[mt][nt][0], o1 = acc[mt][nt][1];
            float o2 = acc[mt][nt][2], o3 = acc[mt][nt][3];
            if (EPI == 2) {
                float2 bb = *(const float2*)(vb1 + c0);
                float2 aa = *(const float2*)(vb2 + c0);
                o0 = e_from_dpre(o0, bb.x, aa.x); o1 = e_from_dpre(o1, bb.y, aa.y);
                o2 = e_from_dpre(o2, bb.x, aa.x); o3 = e_from_dpre(o3, bb.y, aa.y);
            }
            *(float2*)(C + (size_t)r0 * N + c0) = make_float2(o0, o1);
            *(float2*)(C + (size_t)(r0 + 8) * N + c0) = make_float2(o2, o3);
        }
    }
}

// ---------------------------------------------------------------------------
// Small GEMM for dtlow (N=64): BM=128, BN=64, 256 threads, WM=4, WN=2.
// CVTA=true (A=u not pre-rounded), output tf32-rounded.
// ---------------------------------------------------------------------------
__global__ __launch_bounds__(256)
void gemm_dtlow(const float* __restrict__ A, const float* __restrict__ B,
                float* __restrict__ C, int M, int N, int K) {
    constexpr int BN = 64, WM = 4, WN = 2;
    constexpr int MT = 128 / (WM * 16), NT = BN / (WN * 8);
    constexpr int AF4 = (128 * 8) / 256, BF4 = (BN * 8) / 256;

    extern __shared__ float smem[];
    float* As = smem;
    float* Bs = smem + 2 * 128 * SST;

    const int tid = threadIdx.x;
    const int wid = tid >> 5;
    const int lane = tid & 31;
    const int grp = lane >> 2;
    const int qid = lane & 3;
    const int wm = wid / WN;
    const int wn = wid % WN;

    const int bx = blockIdx.x, by = blockIdx.y;
    const float* Ag = A + (size_t)by * 128 * K;
    const float* Bg = B + (size_t)bx * BN * K;

    const uint32_t sA = smem_u32(As);
    const uint32_t sB = smem_u32(Bs);

    float acc[MT][NT][4];
    #pragma unroll
    for (int i = 0; i < MT; i++)
        #pragma unroll
        for (int j = 0; j < NT; j++)
            #pragma unroll
            for (int q = 0; q < 4; q++) acc[i][j][q] = 0.f;

    const int nK = K / GBK;

    #pragma unroll
    for (int t = 0; t < AF4; t++) {
        int f4 = tid + t * 256;
        int row = f4 >> 3, c4 = f4 & 7;
        cp_async16(sA + (row * SST + c4 * 4) * 4, Ag + (size_t)row * K + c4 * 4);
    }
    #pragma unroll
    for (int t = 0; t < BF4; t++) {
        int f4 = tid + t * 256;
        int row = f4 >> 3, c4 = f4 & 7;
        cp_async16(sB + (row * SST + c4 * 4) * 4, Bg + (size_t)row * K + c4 * 4);
    }
    CP_COMMIT();

    int buf = 0;
    for (int kt = 0; kt < nK; kt++) {
        if (kt + 1 < nK) {
            const uint32_t dA = sA + (buf ^ 1) * 128 * SST * 4;
            const uint32_t dB = sB + (buf ^ 1) * BN * SST * 4;
            const int koff = (kt + 1) * GBK;
            #pragma unroll
            for (int t = 0; t < AF4; t++) {
                int f4 = tid + t * 256;
                int row = f4 >> 3, c4 = f4 & 7;
                cp_async16(dA + (row * SST + c4 * 4) * 4, Ag + (size_t)row * K + koff + c4 * 4);
            }
            #pragma unroll
            for (int t = 0; t < BF4; t++) {
                int f4 = tid + t * 256;
                int row = f4 >> 3, c4 = f4 & 7;
                cp_async16(dB + (row * SST + c4 * 4) * 4, Bg + (size_t)row * K + koff + c4 * 4);
            }
            CP_COMMIT();
            CP_WAIT(1);
        } else {
            CP_WAIT(0);
        }
        __syncthreads();

        const float* Ab = As + buf * 128 * SST;
        const float* Bb = Bs + buf * BN * SST;

        #pragma unroll
        for (int s = 0; s < GBK / 8; s++) {
            const int kc2 = s * 8 + 2 * qid;
            uint32_t af[MT][4];
            #pragma unroll
            for (int mt = 0; mt < MT; mt++) {
                const int r0 = wm * (MT * 16) + mt * 16 + grp;
                float2 v0 = *(const float2*)(Ab + r0 * SST + kc2);
                float2 v1 = *(const float2*)(Ab + (r0 + 8) * SST + kc2);
                af[mt][0] = f2tf32(v0.x); af[mt][2] = f2tf32(v0.y);
                af[mt][1] = f2tf32(v1.x); af[mt][3] = f2tf32(v1.y);
            }
            uint32_t bf[NT][2];
            #pragma unroll
            for (int nt = 0; nt < NT; nt++) {
                const int c0 = wn * (NT * 8) + nt * 8 + grp;
                float2 v = *(const float2*)(Bb + c0 * SST + kc2);
                bf[nt][0] = __float_as_uint(v.x);
                bf[nt][1] = __float_as_uint(v.y);
            }
            #pragma unroll
            for (int mt = 0; mt < MT; mt++)
                #pragma unroll
                for (int nt = 0; nt < NT; nt++)
                    mma_tf32(acc[mt][nt], af[mt], bf[nt]);
        }
        __syncthreads();
        buf ^= 1;
    }

    #pragma unroll
    for (int mt = 0; mt < MT; mt++) {
        const int r0 = by * 128 + wm * (MT * 16) + mt * 16 + grp;
        #pragma unroll
        for (int nt = 0; nt < NT; nt++) {
            const int c0 = bx * BN + wn * (NT * 8) + nt * 8 + qid * 2;
            float o0 = __uint_as_float(f2tf32(acc[mt][nt][0]));
            float o1 = __uint_as_float(f2tf32(acc[mt][nt][1]));
            float o2 = __uint_as_float(f2tf32(acc[mt][nt][2]));
            float o3 = __uint_as_float(f2tf32(acc[mt][nt][3]));
            *(float2*)(C + (size_t)r0 * N + c0) = make_float2(o0, o1);
            *(float2*)(C + (size_t)(r0 + 8) * N + c0) = make_float2(o2, o3);
        }
    }
}

// ---------------------------------------------------------------------------
// tf32 rounding prepass
// ---------------------------------------------------------------------------
__global__ __launch_bounds__(256)
void round_tf32_kernel(const float* __restrict__ in, float* __restrict__ out, int n4) {
    int i = blockIdx.x * blockDim.x + threadIdx.x;
    if (i < n4) {
        float4 v = ((const float4*)in)[i];
        v.x = __uint_as_float(f2tf32(v.x));
        v.y = __uint_as_float(f2tf32(v.y));
        v.z = __uint_as_float(f2tf32(v.z));
        v.w = __uint_as_float(f2tf32(v.w));
        ((float4*)out)[i] = v;
    }
}

// ---------------------------------------------------------------------------
// Depthwise causal conv1d + bias + SiLU. float4 over d, 8 l per thread.
// ---------------------------------------------------------------------------
__device__ __forceinline__ float4 silu4(float4 a) {
    a.x = a.x / (1.f + expf(-a.x));
    a.y = a.y / (1.f + expf(-a.y));
    a.z = a.z / (1.f + expf(-a.z));
    a.w = a.w / (1.f + expf(-a.w));
    return a;
}
__device__ __forceinline__ float4 fma4(float4 a, float4 b, float4 c) {
    return make_float4(fmaf(a.x, b.x, c.x), fmaf(a.y, b.y, c.y),
                       fmaf(a.z, b.z, c.z), fmaf(a.w, b.w, c.w));
}

__global__ __launch_bounds__(256)
void conv_silu_kernel(const float* __restrict__ xz,
                      const float* __restrict__ cw,
                      const float* __restrict__ cb,
                      float* __restrict__ u) {
    int idx = blockIdx.x * blockDim.x + threadIdx.x;   // (ROWS/8) * (DI/4)
    int dq = idx & (DI / 4 - 1);
    int g = idx >> 9;
    int l0 = (g & (LL / 8 - 1)) * 8;
    int b = g >> 9;
    size_t bl0 = (size_t)b * LL + l0;
    const int d = dq * 4;

    // per-channel taps: cw rows d..d+3, 4 taps each
    float4 r0 = *(const float4*)(cw + (d + 0) * KC);
    float4 r1 = *(const float4*)(cw + (d + 1) * KC);
    float4 r2 = *(const float4*)(cw + (d + 2) * KC);
    float4 r3 = *(const float4*)(cw + (d + 3) * KC);
    float4 w0 = make_float4(r0.x, r1.x, r2.x, r3.x);
    float4 w1 = make_float4(r0.y, r1.y, r2.y, r3.y);
    float4 w2 = make_float4(r0.z, r1.z, r2.z, r3.z);
    float4 w3 = make_float4(r0.w, r1.w, r2.w, r3.w);
    float4 bias = *(const float4*)(cb + d);

    float4 xm3 = make_float4(0, 0, 0, 0), xm2 = xm3, xm1 = xm3;
    if (l0 > 0) {
        xm3 = *(const float4*)(xz + (bl0 - 3) * (2 * DI) + d);
        xm2 = *(const float4*)(xz + (bl0 - 2) * (2 * DI) + d);
        xm1 = *(const float4*)(xz + (bl0 - 1) * (2 * DI) + d);
    }
    #pragma unroll
    for (int j = 0; j < 8; j++) {
        float4 xc = *(const float4*)(xz + (bl0 + j) * (2 * DI) + d);
        float4 acc = bias;
        acc = fma4(w0, xm3, acc);
        acc = fma4(w1, xm2, acc);
        acc = fma4(w2, xm1, acc);
        acc = fma4(w3, xc, acc);
        *(float4*)(u + (bl0 + j) * DI + d) = silu4(acc);
        xm3 = xm2; xm2 = xm1; xm1 = xc;
    }
}

// ---------------------------------------------------------------------------
// Chunked scan, float4 over d.
// ---------------------------------------------------------------------------
__device__ __forceinline__ float clip1e4(float v) {
    return fminf(fmaxf(v, -1e4f), 1e4f);
}

__global__ __launch_bounds__(256)
void scan_pass1(const float* __restrict__ e, const float* __restrict__ u,
                float* __restrict__ S, float* __restrict__ P) {
    int gid = blockIdx.x * blockDim.x + threadIdx.x;   // BB*NCH*DI/4
    int dq = gid & (DI / 4 - 1);
    int bc = gid / (DI / 4);
    int c = bc & (NCH - 1);
    int b = bc / NCH;
    size_t base = ((size_t)b * LL + (size_t)c * LC) * DI + dq * 4;
    float4 st = make_float4(0, 0, 0, 0);
    float4 pr = make_float4(1, 1, 1, 1);
    #pragma unroll 4
    for (int l = 0; l < LC; l++) {
        float4 et = *(const float4*)(e + base + (size_t)l * DI);
        float4 ut = *(const float4*)(u + base + (size_t)l * DI);
        st.x = clip1e4(fmaf(st.x, et.x, ut.x));
        st.y = clip1e4(fmaf(st.y, et.y, ut.y));
        st.z = clip1e4(fmaf(st.z, et.z, ut.z));
        st.w = clip1e4(fmaf(st.w, et.w, ut.w));
        pr.x *= et.x; pr.y *= et.y; pr.z *= et.z; pr.w *= et.w;
    }
    ((float4*)S)[gid] = st;
    ((float4*)P)[gid] = pr;
}

__global__ __launch_bounds__(128)
void carry_kernel(const float* __restrict__ S, const float* __restrict__ P,
                  float* __restrict__ Cy) {
    int gid = blockIdx.x * blockDim.x + threadIdx.x;   // BB*DI/4
    int b = gid / (DI / 4);
    int dq = gid - b * (DI / 4);
    float4 cr = make_float4(0, 0, 0, 0);
    for (int c = 0; c < NCH; c++) {
        size_t i4 = ((size_t)b * NCH + c) * (DI / 4) + dq;
        ((float4*)Cy)[i4] = cr;
        float4 p = ((const float4*)P)[i4];
        float4 s = ((const float4*)S)[i4];
        cr.x = clip1e4(fmaf(cr.x, p.x, s.x));
        cr.y = clip1e4(fmaf(cr.y, p.y, s.y));
        cr.z = clip1e4(fmaf(cr.z, p.z, s.z));
        cr.w = clip1e4(fmaf(cr.w, p.w, s.w));
    }
}

__global__ __launch_bounds__(256)
void scan_pass2(const float* __restrict__ e, const float* __restrict__ u,
                const float* __restrict__ xz, const float* __restrict__ Dvec,
                const float* __restrict__ Cy, float* __restrict__ yg) {
    int gid = blockIdx.x * blockDim.x + threadIdx.x;
    int dq = gid & (DI / 4 - 1);
    int bc = gid / (DI / 4);
    int c = bc & (NCH - 1);
    int b = bc / NCH;
    size_t base  = ((size_t)b * LL + (size_t)c * LC) * DI + dq * 4;
    size_t zbase = ((size_t)b * LL + (size_t)c * LC) * (2 * DI) + DI + dq * 4;
    float4 Dd = *(const float4*)(Dvec + dq * 4);
    float4 st = ((const float4*)Cy)[gid];
    #pragma unroll 4
    for (int l = 0; l < LC; l++) {
        float4 et = *(const float4*)(e + base + (size_t)l * DI);
        float4 ut = *(const float4*)(u + base + (size_t)l * DI);
        float4 zt = *(const float4*)(xz + zbase + (size_t)l * (2 * DI));
        st.x = clip1e4(fmaf(st.x, et.x, ut.x));
        st.y = clip1e4(fmaf(st.y, et.y, ut.y));
        st.z = clip1e4(fmaf(st.z, et.z, ut.z));
        st.w = clip1e4(fmaf(st.w, et.w, ut.w));
        float4 o;
        o.x = clip1e4(fmaf(ut.x, Dd.x, st.x)) * (zt.x / (1.f + expf(-zt.x)));
        o.y = clip1e4(fmaf(ut.y, Dd.y, st.y)) * (zt.y / (1.f + expf(-zt.y)));
        o.z = clip1e4(fmaf(ut.z, Dd.z, st.z)) * (zt.z / (1.f + expf(-zt.z)));
        o.w = clip1e4(fmaf(ut.w, Dd.w, st.w)) * (zt.w / (1.f + expf(-zt.w)));
        o.x = __uint_as_float(f2tf32(o.x));
        o.y = __uint_as_float(f2tf32(o.y));
        o.z = __uint_as_float(f2tf32(o.z));
        o.w = __uint_as_float(f2tf32(o.w));
        *(float4*)(yg + base + (size_t)l * DI) = o;
    }
}

// ---------------------------------------------------------------------------
// Launch
// ---------------------------------------------------------------------------
extern "C" void kernel_launch(void* const* d_in, const int* in_sizes, int n_in,
                              void* d_out, int out_size) {
    const float* x     = (const float*)d_in[0];
    const float* inw   = (const float*)d_in[1];
    const float* convw = (const float*)d_in[2];
    const float* convb = (const float*)d_in[3];
    const float* xpw   = (const float*)d_in[4];
    const float* dtw   = (const float*)d_in[5];
    const float* dtb   = (const float*)d_in[6];
    const float* alog  = (const float*)d_in[7];
    const float* Dvec  = (const float*)d_in[8];
    const float* outw  = (const float*)d_in[9];
    float* out = (float*)d_out;

    float *xz, *u, *dtlow, *e, *yg, *S, *P, *Cy;
    float *xr, *inwr, *outwr, *xpwr, *dtwr;
    cudaGetSymbolAddress((void**)&xz, g_xz);
    cudaGetSymbolAddress((void**)&u, g_u);
    cudaGetSymbolAddress((void**)&dtlow, g_dtlow);
    cudaGetSymbolAddress((void**)&e, g_e);
    cudaGetSymbolAddress((void**)&yg, g_yg);
    cudaGetSymbolAddress((void**)&S, g_S);
    cudaGetSymbolAddress((void**)&P, g_P);
    cudaGetSymbolAddress((void**)&Cy, g_C);
    cudaGetSymbolAddress((void**)&xr, g_xr);
    cudaGetSymbolAddress((void**)&inwr, g_inwr);
    cudaGetSymbolAddress((void**)&outwr, g_outwr);
    cudaGetSymbolAddress((void**)&xpwr, g_xpwr);
    cudaGetSymbolAddress((void**)&dtwr, g_dtwr);

    const int SM_BIG = 2 * (128 * SST + 256 * SST) * 4;   // 122880
    const int SM_DTL = 2 * (128 * SST + 64 * SST) * 4;    // 61440
    cudaFuncSetAttribute((const void*)gemm_big<0>,
                         cudaFuncAttributeMaxDynamicSharedMemorySize, SM_BIG);
    cudaFuncSetAttribute((const void*)gemm_big<2>,
                         cudaFuncAttributeMaxDynamicSharedMemorySize, SM_BIG);
    cudaFuncSetAttribute((const void*)gemm_dtlow,
                         cudaFuncAttributeMaxDynamicSharedMemorySize, SM_DTL);

    // 0. tf32 rounding prepasses
    round_tf32_kernel<<<(ROWS * DMOD / 4 + 255) / 256, 256>>>(x, xr, ROWS * DMOD / 4);
    round_tf32_kernel<<<(2 * DI * DMOD / 4 + 255) / 256, 256>>>(inw, inwr, 2 * DI * DMOD / 4);
    round_tf32_kernel<<<(DMOD * DI / 4 + 255) / 256, 256>>>(outw, outwr, DMOD * DI / 4);
    round_tf32_kernel<<<(DTR * DI / 4 + 255) / 256, 256>>>(xpw, xpwr, DTR * DI / 4);
    round_tf32_kernel<<<(DI * DTR / 4 + 255) / 256, 256>>>(dtw, dtwr, DI * DTR / 4);

    // 1. in_proj: xz[8192,4096] = xr * inwr^T   (K=1024)
    gemm_big<0><<<dim3((2 * DI) / 256, ROWS / 128), 512, SM_BIG>>>(
        xr, inwr, xz, ROWS, 2 * DI, DMOD, nullptr, nullptr);
    // 2. conv + silu -> u
    conv_silu_kernel<<<(ROWS / 8) * (DI / 4) / 256, 256>>>(xz, convw, convb, u);
    // 3. dtlow[8192,64] = u * xpwr^T  (K=2048)
    gemm_dtlow<<<dim3(1, ROWS / 128), 256, SM_DTL>>>(u, xpwr, dtlow, ROWS, DTR, DI);
    // 4. e[8192,2048] = f(dtlow * dtwr^T + dtb)  (K=64, fused e epilogue)
    gemm_big<2><<<dim3(DI / 256, ROWS / 128), 512, SM_BIG>>>(
        dtlow, dtwr, e, ROWS, DI, DTR, dtb, alog);
    // 5. chunked scan
    scan_pass1<<<(BB * NCH * DI / 4) / 256, 256>>>(e, u, S, P);
    carry_kernel<<<(BB * DI / 4) / 128, 128>>>(S, P, Cy);
    scan_pass2<<<(BB * NCH * DI / 4) / 256, 256>>>(e, u, xz, Dvec, Cy, yg);
    // 6. out_proj: out[8192,1024] = yg * outwr^T  (K=2048)
    gemm_big<0><<<dim3(DMOD / 256, ROWS / 128), 512, SM_BIG>>>(
        yg, outwr, out, ROWS, DMOD, DI, nullptr, nullptr);
}

// round 6
// speedup vs baseline: 1.6538x; 1.6538x over previous
#include <cuda_runtime.h>
#include <cuda_fp16.h>
#include <math.h>
#include <stdint.h>

// ---------------------------------------------------------------------------
// Problem constants
// ---------------------------------------------------------------------------
#define BB 2
#define LL 4096
#define DMOD 1024
#define DI 2048
#define DTR 64
#define KC 4
#define ROWS (BB * LL)       // 8192
#define NCH 64               // scan chunks
#define LC (LL / NCH)        // 64

// ---------------------------------------------------------------------------
// Scratch (device globals; no allocation allowed)
// ---------------------------------------------------------------------------
__device__ float  g_xz[(size_t)ROWS * 2 * DI];     // in_proj out (xi | z), f32
__device__ float  g_u [(size_t)ROWS * DI];         // conv+silu out f32 (scan)
__device__ __half g_uh[(size_t)ROWS * DI];         // conv+silu out f16 (GEMM)
__device__ __half g_dtlowh[(size_t)ROWS * DTR];    // dt_low f16
__device__ float  g_e [(size_t)ROWS * DI];         // decay factors f32
__device__ __half g_ygh[(size_t)ROWS * DI];        // gated scan out f16 (GEMM)
__device__ float  g_S [(size_t)BB * NCH * DI];
__device__ float  g_P [(size_t)BB * NCH * DI];
__device__ float  g_C [(size_t)BB * NCH * DI];
// fp16 operand copies
__device__ __half g_xh  [(size_t)ROWS * DMOD];
__device__ __half g_inwh[(size_t)2 * DI * DMOD];
__device__ __half g_outwh[(size_t)DMOD * DI];
__device__ __half g_xpwh[(size_t)DTR * DI];
__device__ __half g_dtwh[(size_t)DI * DTR];

// ---------------------------------------------------------------------------
// PTX helpers (generic ISA: cp.async + ldmatrix + mma.sync f16 — sm_103-safe)
// ---------------------------------------------------------------------------
__device__ __forceinline__ uint32_t smem_u32(const void* p) {
    uint32_t a;
    asm("{ .reg .u64 t; cvta.to.shared.u64 t, %1; cvt.u32.u64 %0, t; }"
        : "=r"(a) : "l"(p));
    return a;
}
__device__ __forceinline__ void cp_async16(uint32_t dst, const void* src) {
    asm volatile("cp.async.cg.shared.global [%0], [%1], 16;"
                 :: "r"(dst), "l"(src) : "memory");
}
#define CP_COMMIT() asm volatile("cp.async.commit_group;" ::: "memory")
#define CP_WAIT(n)  asm volatile("cp.async.wait_group %0;" :: "n"(n) : "memory")

__device__ __forceinline__ void ldsm_x4(uint32_t* d, uint32_t addr) {
    asm volatile("ldmatrix.sync.aligned.m8n8.x4.shared.b16 {%0,%1,%2,%3}, [%4];"
                 : "=r"(d[0]), "=r"(d[1]), "=r"(d[2]), "=r"(d[3]) : "r"(addr));
}
__device__ __forceinline__ void mma_f16(float* c, const uint32_t* a, const uint32_t* b) {
    asm volatile(
        "mma.sync.aligned.m16n8k16.row.col.f32.f16.f16.f32 "
        "{%0,%1,%2,%3}, {%4,%5,%6,%7}, {%8,%9}, {%0,%1,%2,%3};"
        : "+f"(c[0]), "+f"(c[1]), "+f"(c[2]), "+f"(c[3])
        : "r"(a[0]), "r"(a[1]), "r"(a[2]), "r"(a[3]), "r"(b[0]), "r"(b[1]));
}

__device__ __forceinline__ float e_from_dpre(float acc, float bias, float al) {
    float v = acc + bias;
    float delta = (v > 20.f) ? v : log1pf(expf(v));
    delta = fminf(fmaxf(delta, 1e-6f), 10.f);
    float A = fminf(fmaxf(-expf(al), -10.f), -1e-6f);
    float ev = expf(delta * A);
    return fminf(fmaxf(ev, 1e-6f), 1.f);
}

// ---------------------------------------------------------------------------
// fp16 tensor-core GEMM: C[M,N] = A[M,K]*B[N,K]^T (A,B half row-major).
// BM=128, BN template (128/64). BK=64 halves. 256 threads, 8 warps (2x4),
// warp tile 64 x (BN/4): MT=4, NT=BN/32. Double-buffered cp.async.
// SSTH=72 halves (144B rows) -> conflict-free ldmatrix (9r mod 8 distinct).
// EPI: 0 = f32 store, 2 = fused softplus/exp e-epilogue (vb1=dtb, vb2=A_log),
//      3 = half store to Ch.
// ---------------------------------------------------------------------------
#define SSTH 72
#define BKH  64

template <int BN, int EPI>
__global__ __launch_bounds__(256, 2)
void gemm_f16(const __half* __restrict__ A, const __half* __restrict__ B,
              float* __restrict__ C, __half* __restrict__ Ch,
              int M, int N, int K,
              const float* __restrict__ vb1, const float* __restrict__ vb2) {
    constexpr int MT = 4;
    constexpr int NT = BN / 32;          // n8 tiles per warp
    constexpr int NPAIR = NT / 2;        // ldmatrix.x4 pairs on B side
    constexpr int AF = (128 * 8) / 256;  // 16B chunks per thread for A (=4)
    constexpr int BF = (BN * 8) / 256;   // for B

    extern __shared__ __half smem[];
    const uint32_t sA = smem_u32(smem);                     // bytes
    const uint32_t sB = sA + 2 * 128 * SSTH * 2;

    const int tid = threadIdx.x;
    const int wid = tid >> 5;
    const int lane = tid & 31;
    const int grp = lane >> 2;
    const int qid = lane & 3;
    const int wm = wid >> 2;     // 0..1
    const int wn = wid & 3;      // 0..3

    const int bx = blockIdx.x, by = blockIdx.y;
    const __half* Ag = A + (size_t)by * 128 * K;
    const __half* Bg = B + (size_t)bx * BN * K;

    // ldmatrix per-thread address components
    const int a_row = lane & 15;               // row within m16 tile
    const int a_kb  = (lane >> 4) * 16;        // byte offset for k-half select (8 halves)
    const int b_row = ((lane >> 4) << 3) + (lane & 7);
    const int b_kb  = ((lane >> 3) & 1) * 16;

    float acc[MT][NT][4];
    #pragma unroll
    for (int i = 0; i < MT; i++)
        #pragma unroll
        for (int j = 0; j < NT; j++)
            #pragma unroll
            for (int q = 0; q < 4; q++) acc[i][j][q] = 0.f;

    const int nK = K / BKH;

    // prologue: tile 0 -> buf 0
    #pragma unroll
    for (int t = 0; t < AF; t++) {
        int f = tid + t * 256;
        int row = f >> 3, c = f & 7;
        cp_async16(sA + row * 144 + c * 16, Ag + (size_t)row * K + c * 8);
    }
    #pragma unroll
    for (int t = 0; t < BF; t++) {
        int f = tid + t * 256;
        int row = f >> 3, c = f & 7;
        cp_async16(sB + row * 144 + c * 16, Bg + (size_t)row * K + c * 8);
    }
    CP_COMMIT();

    int buf = 0;
    for (int kt = 0; kt < nK; kt++) {
        if (kt + 1 < nK) {
            const uint32_t dA = sA + (buf ^ 1) * 128 * SSTH * 2;
            const uint32_t dB = sB + (buf ^ 1) * BN * SSTH * 2;
            const int koff = (kt + 1) * BKH;
            #pragma unroll
            for (int t = 0; t < AF; t++) {
                int f = tid + t * 256;
                int row = f >> 3, c = f & 7;
                cp_async16(dA + row * 144 + c * 16, Ag + (size_t)row * K + koff + c * 8);
            }
            #pragma unroll
            for (int t = 0; t < BF; t++) {
                int f = tid + t * 256;
                int row = f >> 3, c = f & 7;
                cp_async16(dB + row * 144 + c * 16, Bg + (size_t)row * K + koff + c * 8);
            }
            CP_COMMIT();
            CP_WAIT(1);
        } else {
            CP_WAIT(0);
        }
        __syncthreads();

        const uint32_t Ab = sA + buf * 128 * SSTH * 2;
        const uint32_t Bb = sB + buf * BN * SSTH * 2;

        // per-thread ldmatrix base addresses (k0 = 0)
        uint32_t addrA[MT], addrB[NPAIR];
        #pragma unroll
        for (int mt = 0; mt < MT; mt++)
            addrA[mt] = Ab + (wm * 64 + mt * 16 + a_row) * 144 + a_kb;
        #pragma unroll
        for (int p = 0; p < NPAIR; p++)
            addrB[p] = Bb + (wn * (NT * 8) + p * 16 + b_row) * 144 + b_kb;

        #pragma unroll
        for (int s = 0; s < BKH / 16; s++) {        // 4 k16-steps
            uint32_t af[MT][4];
            #pragma unroll
            for (int mt = 0; mt < MT; mt++)
                ldsm_x4(af[mt], addrA[mt] + s * 32);
            uint32_t bf[NPAIR][4];
            #pragma unroll
            for (int p = 0; p < NPAIR; p++)
                ldsm_x4(bf[p], addrB[p] + s * 32);
            #pragma unroll
            for (int mt = 0; mt < MT; mt++)
                #pragma unroll
                for (int nt = 0; nt < NT; nt++)
                    mma_f16(acc[mt][nt], af[mt], &bf[nt >> 1][(nt & 1) * 2]);
        }
        __syncthreads();
        buf ^= 1;
    }

    // epilogue
    #pragma unroll
    for (int mt = 0; mt < MT; mt++) {
        const int r0 = by * 128 + wm * 64 + mt * 16 + grp;
        #pragma unroll
        for (int nt = 0; nt < NT; nt++) {
            const int c0 = bx * BN + wn * (NT * 8) + nt * 8 + qid * 2;
            float o0 = acc[mt][nt][0], o1 = acc[mt][nt][1];
            float o2 = acc[mt][nt][2], o3 = acc[mt][nt][3];
            if (EPI == 2) {
                float2 bb = *(const float2*)(vb1 + c0);
                float2 aa = *(const float2*)(vb2 + c0);
                o0 = e_from_dpre(o0, bb.x, aa.x); o1 = e_from_dpre(o1, bb.y, aa.y);
                o2 = e_from_dpre(o2, bb.x, aa.x); o3 = e_from_dpre(o3, bb.y, aa.y);
            }
            if (EPI == 3) {
                *(__half2*)(Ch + (size_t)r0 * N + c0) = __floats2half2_rn(o0, o1);
                *(__half2*)(Ch + (size_t)(r0 + 8) * N + c0) = __floats2half2_rn(o2, o3);
            } else {
                *(float2*)(C + (size_t)r0 * N + c0) = make_float2(o0, o1);
                *(float2*)(C + (size_t)(r0 + 8) * N + c0) = make_float2(o2, o3);
            }
        }
    }
}

// ---------------------------------------------------------------------------
// f32 -> f16 conversion prepass (8 elems per thread)
// ---------------------------------------------------------------------------
__global__ __launch_bounds__(256)
void to_half_kernel(const float* __restrict__ in, __half* __restrict__ out, int n8) {
    int i = blockIdx.x * blockDim.x + threadIdx.x;
    if (i < n8) {
        float4 v0 = ((const float4*)in)[2 * i];
        float4 v1 = ((const float4*)in)[2 * i + 1];
        __half2 h0 = __floats2half2_rn(v0.x, v0.y);
        __half2 h1 = __floats2half2_rn(v0.z, v0.w);
        __half2 h2 = __floats2half2_rn(v1.x, v1.y);
        __half2 h3 = __floats2half2_rn(v1.z, v1.w);
        uint4 o;
        o.x = *(uint32_t*)&h0; o.y = *(uint32_t*)&h1;
        o.z = *(uint32_t*)&h2; o.w = *(uint32_t*)&h3;
        ((uint4*)out)[i] = o;
    }
}

// ---------------------------------------------------------------------------
// Depthwise causal conv1d + bias + SiLU. float4 over d, 8 l per thread.
// Writes u (f32, scan) and uh (f16, GEMM).
// ---------------------------------------------------------------------------
__device__ __forceinline__ float4 silu4(float4 a) {
    a.x = a.x / (1.f + expf(-a.x));
    a.y = a.y / (1.f + expf(-a.y));
    a.z = a.z / (1.f + expf(-a.z));
    a.w = a.w / (1.f + expf(-a.w));
    return a;
}
__device__ __forceinline__ float4 fma4(float4 a, float4 b, float4 c) {
    return make_float4(fmaf(a.x, b.x, c.x), fmaf(a.y, b.y, c.y),
                       fmaf(a.z, b.z, c.z), fmaf(a.w, b.w, c.w));
}
__device__ __forceinline__ void store_half4(__half* p, float4 v) {
    __half2 lo = __floats2half2_rn(v.x, v.y);
    __half2 hi = __floats2half2_rn(v.z, v.w);
    uint2 o; o.x = *(uint32_t*)&lo; o.y = *(uint32_t*)&hi;
    *(uint2*)p = o;
}

__global__ __launch_bounds__(256)
void conv_silu_kernel(const float* __restrict__ xz,
                      const float* __restrict__ cw,
                      const float* __restrict__ cb,
                      float* __restrict__ u, __half* __restrict__ uh) {
    int idx = blockIdx.x * blockDim.x + threadIdx.x;   // (ROWS/8) * (DI/4)
    int dq = idx & (DI / 4 - 1);
    int g = idx >> 9;
    int l0 = (g & (LL / 8 - 1)) * 8;
    int b = g >> 9;
    size_t bl0 = (size_t)b * LL + l0;
    const int d = dq * 4;

    float4 r0 = *(const float4*)(cw + (d + 0) * KC);
    float4 r1 = *(const float4*)(cw + (d + 1) * KC);
    float4 r2 = *(const float4*)(cw + (d + 2) * KC);
    float4 r3 = *(const float4*)(cw + (d + 3) * KC);
    float4 w0 = make_float4(r0.x, r1.x, r2.x, r3.x);
    float4 w1 = make_float4(r0.y, r1.y, r2.y, r3.y);
    float4 w2 = make_float4(r0.z, r1.z, r2.z, r3.z);
    float4 w3 = make_float4(r0.w, r1.w, r2.w, r3.w);
    float4 bias = *(const float4*)(cb + d);

    float4 xm3 = make_float4(0, 0, 0, 0), xm2 = xm3, xm1 = xm3;
    if (l0 > 0) {
        xm3 = *(const float4*)(xz + (bl0 - 3) * (2 * DI) + d);
        xm2 = *(const float4*)(xz + (bl0 - 2) * (2 * DI) + d);
        xm1 = *(const float4*)(xz + (bl0 - 1) * (2 * DI) + d);
    }
    #pragma unroll
    for (int j = 0; j < 8; j++) {
        float4 xc = *(const float4*)(xz + (bl0 + j) * (2 * DI) + d);
        float4 acc = bias;
        acc = fma4(w0, xm3, acc);
        acc = fma4(w1, xm2, acc);
        acc = fma4(w2, xm1, acc);
        acc = fma4(w3, xc, acc);
        float4 s = silu4(acc);
        *(float4*)(u + (bl0 + j) * DI + d) = s;
        store_half4(uh + (bl0 + j) * DI + d, s);
        xm3 = xm2; xm2 = xm1; xm1 = xc;
    }
}

// ---------------------------------------------------------------------------
// Chunked scan, float4 over d.
// ---------------------------------------------------------------------------
__device__ __forceinline__ float clip1e4(float v) {
    return fminf(fmaxf(v, -1e4f), 1e4f);
}

__global__ __launch_bounds__(256)
void scan_pass1(const float* __restrict__ e, const float* __restrict__ u,
                float* __restrict__ S, float* __restrict__ P) {
    int gid = blockIdx.x * blockDim.x + threadIdx.x;
    int dq = gid & (DI / 4 - 1);
    int bc = gid / (DI / 4);
    int c = bc & (NCH - 1);
    int b = bc / NCH;
    size_t base = ((size_t)b * LL + (size_t)c * LC) * DI + dq * 4;
    float4 st = make_float4(0, 0, 0, 0);
    float4 pr = make_float4(1, 1, 1, 1);
    #pragma unroll 4
    for (int l = 0; l < LC; l++) {
        float4 et = *(const float4*)(e + base + (size_t)l * DI);
        float4 ut = *(const float4*)(u + base + (size_t)l * DI);
        st.x = clip1e4(fmaf(st.x, et.x, ut.x));
        st.y = clip1e4(fmaf(st.y, et.y, ut.y));
        st.z = clip1e4(fmaf(st.z, et.z, ut.z));
        st.w = clip1e4(fmaf(st.w, et.w, ut.w));
        pr.x *= et.x; pr.y *= et.y; pr.z *= et.z; pr.w *= et.w;
    }
    ((float4*)S)[gid] = st;
    ((float4*)P)[gid] = pr;
}

__global__ __launch_bounds__(128)
void carry_kernel(const float* __restrict__ S, const float* __restrict__ P,
                  float* __restrict__ Cy) {
    int gid = blockIdx.x * blockDim.x + threadIdx.x;
    int b = gid / (DI / 4);
    int dq = gid - b * (DI / 4);
    float4 cr = make_float4(0, 0, 0, 0);
    for (int c = 0; c < NCH; c++) {
        size_t i4 = ((size_t)b * NCH + c) * (DI / 4) + dq;
        ((float4*)Cy)[i4] = cr;
        float4 p = ((const float4*)P)[i4];
        float4 s = ((const float4*)S)[i4];
        cr.x = clip1e4(fmaf(cr.x, p.x, s.x));
        cr.y = clip1e4(fmaf(cr.y, p.y, s.y));
        cr.z = clip1e4(fmaf(cr.z, p.z, s.z));
        cr.w = clip1e4(fmaf(cr.w, p.w, s.w));
    }
}

__global__ __launch_bounds__(256)
void scan_pass2(const float* __restrict__ e, const float* __restrict__ u,
                const float* __restrict__ xz, const float* __restrict__ Dvec,
                const float* __restrict__ Cy, __half* __restrict__ ygh) {
    int gid = blockIdx.x * blockDim.x + threadIdx.x;
    int dq = gid & (DI / 4 - 1);
    int bc = gid / (DI / 4);
    int c = bc & (NCH - 1);
    int b = bc / NCH;
    size_t base  = ((size_t)b * LL + (size_t)c * LC) * DI + dq * 4;
    size_t zbase = ((size_t)b * LL + (size_t)c * LC) * (2 * DI) + DI + dq * 4;
    float4 Dd = *(const float4*)(Dvec + dq * 4);
    float4 st = ((const float4*)Cy)[gid];
    #pragma unroll 4
    for (int l = 0; l < LC; l++) {
        float4 et = *(const float4*)(e + base + (size_t)l * DI);
        float4 ut = *(const float4*)(u + base + (size_t)l * DI);
        float4 zt = *(const float4*)(xz + zbase + (size_t)l * (2 * DI));
        st.x = clip1e4(fmaf(st.x, et.x, ut.x));
        st.y = clip1e4(fmaf(st.y, et.y, ut.y));
        st.z = clip1e4(fmaf(st.z, et.z, ut.z));
        st.w = clip1e4(fmaf(st.w, et.w, ut.w));
        float4 o;
        o.x = clip1e4(fmaf(ut.x, Dd.x, st.x)) * (zt.x / (1.f + expf(-zt.x)));
        o.y = clip1e4(fmaf(ut.y, Dd.y, st.y)) * (zt.y / (1.f + expf(-zt.y)));
        o.z = clip1e4(fmaf(ut.z, Dd.z, st.z)) * (zt.z / (1.f + expf(-zt.z)));
        o.w = clip1e4(fmaf(ut.w, Dd.w, st.w)) * (zt.w / (1.f + expf(-zt.w)));
        store_half4(ygh + base + (size_t)l * DI, o);
    }
}

// ---------------------------------------------------------------------------
// Launch
// ---------------------------------------------------------------------------
extern "C" void kernel_launch(void* const* d_in, const int* in_sizes, int n_in,
                              void* d_out, int out_size) {
    const float* x     = (const float*)d_in[0];
    const float* inw   = (const float*)d_in[1];
    const float* convw = (const float*)d_in[2];
    const float* convb = (const float*)d_in[3];
    const float* xpw   = (const float*)d_in[4];
    const float* dtw   = (const float*)d_in[5];
    const float* dtb   = (const float*)d_in[6];
    const float* alog  = (const float*)d_in[7];
    const float* Dvec  = (const float*)d_in[8];
    const float* outw  = (const float*)d_in[9];
    float* out = (float*)d_out;

    float *xz, *u, *e, *S, *P, *Cy;
    __half *uh, *dtlowh, *ygh, *xh, *inwh, *outwh, *xpwh, *dtwh;
    cudaGetSymbolAddress((void**)&xz, g_xz);
    cudaGetSymbolAddress((void**)&u, g_u);
    cudaGetSymbolAddress((void**)&uh, g_uh);
    cudaGetSymbolAddress((void**)&dtlowh, g_dtlowh);
    cudaGetSymbolAddress((void**)&e, g_e);
    cudaGetSymbolAddress((void**)&ygh, g_ygh);
    cudaGetSymbolAddress((void**)&S, g_S);
    cudaGetSymbolAddress((void**)&P, g_P);
    cudaGetSymbolAddress((void**)&Cy, g_C);
    cudaGetSymbolAddress((void**)&xh, g_xh);
    cudaGetSymbolAddress((void**)&inwh, g_inwh);
    cudaGetSymbolAddress((void**)&outwh, g_outwh);
    cudaGetSymbolAddress((void**)&xpwh, g_xpwh);
    cudaGetSymbolAddress((void**)&dtwh, g_dtwh);

    const int SM128 = 2 * (128 * SSTH + 128 * SSTH) * 2;   // 73728 B
    const int SM64  = 2 * (128 * SSTH + 64 * SSTH) * 2;    // 55296 B
    cudaFuncSetAttribute((const void*)gemm_f16<128, 0>,
                         cudaFuncAttributeMaxDynamicSharedMemorySize, SM128);
    cudaFuncSetAttribute((const void*)gemm_f16<128, 2>,
                         cudaFuncAttributeMaxDynamicSharedMemorySize, SM128);
    cudaFuncSetAttribute((const void*)gemm_f16<64, 3>,
                         cudaFuncAttributeMaxDynamicSharedMemorySize, SM64);

    // 0. f32 -> f16 conversion prepasses
    to_half_kernel<<<(ROWS * DMOD / 8 + 255) / 256, 256>>>(x, xh, ROWS * DMOD / 8);
    to_half_kernel<<<(2 * DI * DMOD / 8 + 255) / 256, 256>>>(inw, inwh, 2 * DI * DMOD / 8);
    to_half_kernel<<<(DMOD * DI / 8 + 255) / 256, 256>>>(outw, outwh, DMOD * DI / 8);
    to_half_kernel<<<(DTR * DI / 8 + 255) / 256, 256>>>(xpw, xpwh, DTR * DI / 8);
    to_half_kernel<<<(DI * DTR / 8 + 255) / 256, 256>>>(dtw, dtwh, DI * DTR / 8);

    // 1. in_proj: xz[8192,4096] = xh * inwh^T   (K=1024)
    gemm_f16<128, 0><<<dim3((2 * DI) / 128, ROWS / 128), 256, SM128>>>(
        xh, inwh, xz, nullptr, ROWS, 2 * DI, DMOD, nullptr, nullptr);
    // 2. conv + silu -> u (f32) + uh (f16)
    conv_silu_kernel<<<(ROWS / 8) * (DI / 4) / 256, 256>>>(xz, convw, convb, u, uh);
    // 3. dtlow[8192,64] = uh * xpwh^T  (K=2048) -> half
    gemm_f16<64, 3><<<dim3(1, ROWS / 128), 256, SM64>>>(
        uh, xpwh, nullptr, dtlowh, ROWS, DTR, DI, nullptr, nullptr);
    // 4. e[8192,2048] = f(dtlowh * dtwh^T + dtb)  (K=64, fused e epilogue)
    gemm_f16<128, 2><<<dim3(DI / 128, ROWS / 128), 256, SM128>>>(
        dtlowh, dtwh, e, nullptr, ROWS, DI, DTR, dtb, alog);
    // 5. chunked scan
    scan_pass1<<<(BB * NCH * DI / 4) / 256, 256>>>(e, u, S, P);
    carry_kernel<<<(BB * DI / 4) / 128, 128>>>(S, P, Cy);
    scan_pass2<<<(BB * NCH * DI / 4) / 256, 256>>>(e, u, xz, Dvec, Cy, ygh);
    // 6. out_proj: out[8192,1024] = ygh * outwh^T  (K=2048)
    gemm_f16<128, 0><<<dim3(DMOD / 128, ROWS / 128), 256, SM128>>>(
        ygh, outwh, out, nullptr, ROWS, DMOD, DI, nullptr, nullptr);
}

// round 7
// speedup vs baseline: 1.7071x; 1.0322x over previous
#include <cuda_runtime.h>
#include <cuda_fp16.h>
#include <math.h>
#include <stdint.h>

// ---------------------------------------------------------------------------
// Problem constants
// ---------------------------------------------------------------------------
#define BB 2
#define LL 4096
#define DMOD 1024
#define DI 2048
#define DTR 64
#define KC 4
#define ROWS (BB * LL)       // 8192
#define NCH 64               // scan chunks
#define LC (LL / NCH)        // 64

// ---------------------------------------------------------------------------
// Scratch (device globals; no allocation allowed)
// ---------------------------------------------------------------------------
__device__ float  g_xz[(size_t)ROWS * 2 * DI];     // in_proj out (xi | z), f32
__device__ __half g_uh[(size_t)ROWS * DI];         // conv+silu out f16
__device__ __half g_dtlowh[(size_t)ROWS * DTR];    // dt_low f16
__device__ float  g_e [(size_t)ROWS * DI];         // decay factors f32
__device__ __half g_ygh[(size_t)ROWS * DI];        // gated scan out f16
__device__ float  g_S [(size_t)BB * NCH * DI];
__device__ float  g_P [(size_t)BB * NCH * DI];
__device__ float  g_C [(size_t)BB * NCH * DI];
// fp16 operand copies
__device__ __half g_xh  [(size_t)ROWS * DMOD];
__device__ __half g_inwh[(size_t)2 * DI * DMOD];
__device__ __half g_outwh[(size_t)DMOD * DI];
__device__ __half g_xpwh[(size_t)DTR * DI];
__device__ __half g_dtwh[(size_t)DI * DTR];

// ---------------------------------------------------------------------------
// PTX helpers (generic ISA: cp.async + ldmatrix + mma.sync f16 — sm_103-safe)
// ---------------------------------------------------------------------------
__device__ __forceinline__ uint32_t smem_u32(const void* p) {
    uint32_t a;
    asm("{ .reg .u64 t; cvta.to.shared.u64 t, %1; cvt.u32.u64 %0, t; }"
        : "=r"(a) : "l"(p));
    return a;
}
__device__ __forceinline__ void cp_async16(uint32_t dst, const void* src) {
    asm volatile("cp.async.cg.shared.global [%0], [%1], 16;"
                 :: "r"(dst), "l"(src) : "memory");
}
#define CP_COMMIT() asm volatile("cp.async.commit_group;" ::: "memory")
#define CP_WAIT(n)  asm volatile("cp.async.wait_group %0;" :: "n"(n) : "memory")

__device__ __forceinline__ void ldsm_x4(uint32_t* d, uint32_t addr) {
    asm volatile("ldmatrix.sync.aligned.m8n8.x4.shared.b16 {%0,%1,%2,%3}, [%4];"
                 : "=r"(d[0]), "=r"(d[1]), "=r"(d[2]), "=r"(d[3]) : "r"(addr));
}
__device__ __forceinline__ void mma_f16(float* c, const uint32_t* a, const uint32_t* b) {
    asm volatile(
        "mma.sync.aligned.m16n8k16.row.col.f32.f16.f16.f32 "
        "{%0,%1,%2,%3}, {%4,%5,%6,%7}, {%8,%9}, {%0,%1,%2,%3};"
        : "+f"(c[0]), "+f"(c[1]), "+f"(c[2]), "+f"(c[3])
        : "r"(a[0]), "r"(a[1]), "r"(a[2]), "r"(a[3]), "r"(b[0]), "r"(b[1]));
}

__device__ __forceinline__ float e_from_dpre(float acc, float bias, float al) {
    float v = acc + bias;
    float delta = (v > 20.f) ? v : log1pf(expf(v));
    delta = fminf(fmaxf(delta, 1e-6f), 10.f);
    float A = fminf(fmaxf(-expf(al), -10.f), -1e-6f);
    float ev = expf(delta * A);
    return fminf(fmaxf(ev, 1e-6f), 1.f);
}
__device__ __forceinline__ float clip1e4(float v) {
    return fminf(fmaxf(v, -1e4f), 1e4f);
}

// ---------------------------------------------------------------------------
// fp16 tensor-core GEMM: C[M,N] = A[M,K]*B[N,K]^T (A,B half row-major).
// BM=128, BN template. BK=64 halves. 256 threads, 8 warps (2x4).
// SSTH=72 halves (144B rows) -> conflict-free ldmatrix.
// EPI: 0 = f32 store
//      2 = fused e-epilogue (softplus/exp with vb1=dtb, vb2=A_log) PLUS
//          fused scan pass1: tile = 2 chunks x 128 d; e stashed in smem,
//          each thread scans one (chunk, d) column using U (=uh), writes Sp/Pp.
//      3 = half store to Ch.
// ---------------------------------------------------------------------------
#define SSTH 72
#define BKH  64
#define EST  132   // e-tile smem stride (floats)

template <int BN, int EPI>
__global__ __launch_bounds__(256, 2)
void gemm_f16(const __half* __restrict__ A, const __half* __restrict__ B,
              float* __restrict__ C, __half* __restrict__ Ch,
              int M, int N, int K,
              const float* __restrict__ vb1, const float* __restrict__ vb2,
              const __half* __restrict__ U,
              float* __restrict__ Sp, float* __restrict__ Pp) {
    constexpr int MT = 4;
    constexpr int NT = BN / 32;
    constexpr int NPAIR = NT / 2;
    constexpr int AF = (128 * 8) / 256;
    constexpr int BF = (BN * 8) / 256;

    extern __shared__ __half smem[];
    const uint32_t sA = smem_u32(smem);
    const uint32_t sB = sA + 2 * 128 * SSTH * 2;

    const int tid = threadIdx.x;
    const int wid = tid >> 5;
    const int lane = tid & 31;
    const int grp = lane >> 2;
    const int qid = lane & 3;
    const int wm = wid >> 2;
    const int wn = wid & 3;

    const int bx = blockIdx.x, by = blockIdx.y;
    const __half* Ag = A + (size_t)by * 128 * K;
    const __half* Bg = B + (size_t)bx * BN * K;

    const int a_row = lane & 15;
    const int a_kb  = (lane >> 4) * 16;
    const int b_row = ((lane >> 4) << 3) + (lane & 7);
    const int b_kb  = ((lane >> 3) & 1) * 16;

    float acc[MT][NT][4];
    #pragma unroll
    for (int i = 0; i < MT; i++)
        #pragma unroll
        for (int j = 0; j < NT; j++)
            #pragma unroll
            for (int q = 0; q < 4; q++) acc[i][j][q] = 0.f;

    const int nK = K / BKH;

    #pragma unroll
    for (int t = 0; t < AF; t++) {
        int f = tid + t * 256;
        int row = f >> 3, c = f & 7;
        cp_async16(sA + row * 144 + c * 16, Ag + (size_t)row * K + c * 8);
    }
    #pragma unroll
    for (int t = 0; t < BF; t++) {
        int f = tid + t * 256;
        int row = f >> 3, c = f & 7;
        cp_async16(sB + row * 144 + c * 16, Bg + (size_t)row * K + c * 8);
    }
    CP_COMMIT();

    int buf = 0;
    for (int kt = 0; kt < nK; kt++) {
        if (kt + 1 < nK) {
            const uint32_t dA = sA + (buf ^ 1) * 128 * SSTH * 2;
            const uint32_t dB = sB + (buf ^ 1) * BN * SSTH * 2;
            const int koff = (kt + 1) * BKH;
            #pragma unroll
            for (int t = 0; t < AF; t++) {
                int f = tid + t * 256;
                int row = f >> 3, c = f & 7;
                cp_async16(dA + row * 144 + c * 16, Ag + (size_t)row * K + koff + c * 8);
            }
            #pragma unroll
            for (int t = 0; t < BF; t++) {
                int f = tid + t * 256;
                int row = f >> 3, c = f & 7;
                cp_async16(dB + row * 144 + c * 16, Bg + (size_t)row * K + koff + c * 8);
            }
            CP_COMMIT();
            CP_WAIT(1);
        } else {
            CP_WAIT(0);
        }
        __syncthreads();

        const uint32_t Ab = sA + buf * 128 * SSTH * 2;
        const uint32_t Bb = sB + buf * BN * SSTH * 2;

        uint32_t addrA[MT], addrB[NPAIR];
        #pragma unroll
        for (int mt = 0; mt < MT; mt++)
            addrA[mt] = Ab + (wm * 64 + mt * 16 + a_row) * 144 + a_kb;
        #pragma unroll
        for (int p = 0; p < NPAIR; p++)
            addrB[p] = Bb + (wn * (NT * 8) + p * 16 + b_row) * 144 + b_kb;

        #pragma unroll
        for (int s = 0; s < BKH / 16; s++) {
            uint32_t af[MT][4];
            #pragma unroll
            for (int mt = 0; mt < MT; mt++)
                ldsm_x4(af[mt], addrA[mt] + s * 32);
            uint32_t bf[NPAIR][4];
            #pragma unroll
            for (int p = 0; p < NPAIR; p++)
                ldsm_x4(bf[p], addrB[p] + s * 32);
            #pragma unroll
            for (int mt = 0; mt < MT; mt++)
                #pragma unroll
                for (int nt = 0; nt < NT; nt++)
                    mma_f16(acc[mt][nt], af[mt], &bf[nt >> 1][(nt & 1) * 2]);
        }
        __syncthreads();
        buf ^= 1;
    }

    float* se = (float*)smem;   // e-tile stash for EPI==2 (128 x EST)

    // epilogue
    #pragma unroll
    for (int mt = 0; mt < MT; mt++) {
        const int rl = wm * 64 + mt * 16 + grp;
        const int r0 = by * 128 + rl;
        #pragma unroll
        for (int nt = 0; nt < NT; nt++) {
            const int cl = wn * (NT * 8) + nt * 8 + qid * 2;
            const int c0 = bx * BN + cl;
            float o0 = acc[mt][nt][0], o1 = acc[mt][nt][1];
            float o2 = acc[mt][nt][2], o3 = acc[mt][nt][3];
            if (EPI == 2) {
                float2 bb = *(const float2*)(vb1 + c0);
                float2 aa = *(const float2*)(vb2 + c0);
                o0 = e_from_dpre(o0, bb.x, aa.x); o1 = e_from_dpre(o1, bb.y, aa.y);
                o2 = e_from_dpre(o2, bb.x, aa.x); o3 = e_from_dpre(o3, bb.y, aa.y);
                *(float2*)(se + rl * EST + cl) = make_float2(o0, o1);
                *(float2*)(se + (rl + 8) * EST + cl) = make_float2(o2, o3);
            }
            if (EPI == 3) {
                *(__half2*)(Ch + (size_t)r0 * N + c0) = __floats2half2_rn(o0, o1);
                *(__half2*)(Ch + (size_t)(r0 + 8) * N + c0) = __floats2half2_rn(o2, o3);
            } else {
                *(float2*)(C + (size_t)r0 * N + c0) = make_float2(o0, o1);
                *(float2*)(C + (size_t)(r0 + 8) * N + c0) = make_float2(o2, o3);
            }
        }
    }

    if (EPI == 2) {
        // fused scan pass1: 2 chunks x 128 d per block, one thread each.
        __syncthreads();
        const int ci = tid >> 7;          // chunk within tile (0..1)
        const int dl = tid & 127;         // local d
        const size_t row0 = (size_t)by * 128 + ci * 64;
        const int b = (int)(row0 >> 12);          // /4096
        const int c = (int)((row0 & 4095) >> 6);  // /64
        const int d = bx * BN + dl;
        const __half* up = U + row0 * N + d;
        const float* ep = se + ci * 64 * EST + dl;
        float st = 0.f, pr = 1.f;
        #pragma unroll 8
        for (int l = 0; l < LC; l++) {
            float et = ep[l * EST];
            float ut = __half2float(up[(size_t)l * N]);
            st = clip1e4(fmaf(st, et, ut));
            pr *= et;
        }
        const size_t gi = ((size_t)b * NCH + c) * DI + d;
        Sp[gi] = st;
        Pp[gi] = pr;
    }
}

// ---------------------------------------------------------------------------
// f32 -> f16 conversion prepass
// ---------------------------------------------------------------------------
__global__ __launch_bounds__(256)
void to_half_kernel(const float* __restrict__ in, __half* __restrict__ out, int n8) {
    int i = blockIdx.x * blockDim.x + threadIdx.x;
    if (i < n8) {
        float4 v0 = ((const float4*)in)[2 * i];
        float4 v1 = ((const float4*)in)[2 * i + 1];
        __half2 h0 = __floats2half2_rn(v0.x, v0.y);
        __half2 h1 = __floats2half2_rn(v0.z, v0.w);
        __half2 h2 = __floats2half2_rn(v1.x, v1.y);
        __half2 h3 = __floats2half2_rn(v1.z, v1.w);
        uint4 o;
        o.x = *(uint32_t*)&h0; o.y = *(uint32_t*)&h1;
        o.z = *(uint32_t*)&h2; o.w = *(uint32_t*)&h3;
        ((uint4*)out)[i] = o;
    }
}

// ---------------------------------------------------------------------------
// Depthwise causal conv1d + bias + SiLU. float4 over d, 8 l per thread.
// Writes uh (f16) only.
// ---------------------------------------------------------------------------
__device__ __forceinline__ float4 silu4(float4 a) {
    a.x = a.x / (1.f + expf(-a.x));
    a.y = a.y / (1.f + expf(-a.y));
    a.z = a.z / (1.f + expf(-a.z));
    a.w = a.w / (1.f + expf(-a.w));
    return a;
}
__device__ __forceinline__ float4 fma4(float4 a, float4 b, float4 c) {
    return make_float4(fmaf(a.x, b.x, c.x), fmaf(a.y, b.y, c.y),
                       fmaf(a.z, b.z, c.z), fmaf(a.w, b.w, c.w));
}
__device__ __forceinline__ void store_half4(__half* p, float4 v) {
    __half2 lo = __floats2half2_rn(v.x, v.y);
    __half2 hi = __floats2half2_rn(v.z, v.w);
    uint2 o; o.x = *(uint32_t*)&lo; o.y = *(uint32_t*)&hi;
    *(uint2*)p = o;
}
__device__ __forceinline__ float4 load_half4(const __half* p) {
    uint2 v = *(const uint2*)p;
    __half2 h0 = *(__half2*)&v.x;
    __half2 h1 = *(__half2*)&v.y;
    float2 f0 = __half22float2(h0);
    float2 f1 = __half22float2(h1);
    return make_float4(f0.x, f0.y, f1.x, f1.y);
}

__global__ __launch_bounds__(256)
void conv_silu_kernel(const float* __restrict__ xz,
                      const float* __restrict__ cw,
                      const float* __restrict__ cb,
                      __half* __restrict__ uh) {
    int idx = blockIdx.x * blockDim.x + threadIdx.x;
    int dq = idx & (DI / 4 - 1);
    int g = idx >> 9;
    int l0 = (g & (LL / 8 - 1)) * 8;
    int b = g >> 9;
    size_t bl0 = (size_t)b * LL + l0;
    const int d = dq * 4;

    float4 r0 = *(const float4*)(cw + (d + 0) * KC);
    float4 r1 = *(const float4*)(cw + (d + 1) * KC);
    float4 r2 = *(const float4*)(cw + (d + 2) * KC);
    float4 r3 = *(const float4*)(cw + (d + 3) * KC);
    float4 w0 = make_float4(r0.x, r1.x, r2.x, r3.x);
    float4 w1 = make_float4(r0.y, r1.y, r2.y, r3.y);
    float4 w2 = make_float4(r0.z, r1.z, r2.z, r3.z);
    float4 w3 = make_float4(r0.w, r1.w, r2.w, r3.w);
    float4 bias = *(const float4*)(cb + d);

    float4 xm3 = make_float4(0, 0, 0, 0), xm2 = xm3, xm1 = xm3;
    if (l0 > 0) {
        xm3 = *(const float4*)(xz + (bl0 - 3) * (2 * DI) + d);
        xm2 = *(const float4*)(xz + (bl0 - 2) * (2 * DI) + d);
        xm1 = *(const float4*)(xz + (bl0 - 1) * (2 * DI) + d);
    }
    #pragma unroll
    for (int j = 0; j < 8; j++) {
        float4 xc = *(const float4*)(xz + (bl0 + j) * (2 * DI) + d);
        float4 acc = bias;
        acc = fma4(w0, xm3, acc);
        acc = fma4(w1, xm2, acc);
        acc = fma4(w2, xm1, acc);
        acc = fma4(w3, xc, acc);
        store_half4(uh + (bl0 + j) * DI + d, silu4(acc));
        xm3 = xm2; xm2 = xm1; xm1 = xc;
    }
}

// ---------------------------------------------------------------------------
// Carry + scan pass2
// ---------------------------------------------------------------------------
__global__ __launch_bounds__(128)
void carry_kernel(const float* __restrict__ S, const float* __restrict__ P,
                  float* __restrict__ Cy) {
    int gid = blockIdx.x * blockDim.x + threadIdx.x;
    int b = gid / (DI / 4);
    int dq = gid - b * (DI / 4);
    float4 cr = make_float4(0, 0, 0, 0);
    for (int c = 0; c < NCH; c++) {
        size_t i4 = ((size_t)b * NCH + c) * (DI / 4) + dq;
        ((float4*)Cy)[i4] = cr;
        float4 p = ((const float4*)P)[i4];
        float4 s = ((const float4*)S)[i4];
        cr.x = clip1e4(fmaf(cr.x, p.x, s.x));
        cr.y = clip1e4(fmaf(cr.y, p.y, s.y));
        cr.z = clip1e4(fmaf(cr.z, p.z, s.z));
        cr.w = clip1e4(fmaf(cr.w, p.w, s.w));
    }
}

__global__ __launch_bounds__(256)
void scan_pass2(const float* __restrict__ e, const __half* __restrict__ uh,
                const float* __restrict__ xz, const float* __restrict__ Dvec,
                const float* __restrict__ Cy, __half* __restrict__ ygh) {
    int gid = blockIdx.x * blockDim.x + threadIdx.x;
    int dq = gid & (DI / 4 - 1);
    int bc = gid / (DI / 4);
    int c = bc & (NCH - 1);
    int b = bc / NCH;
    size_t base  = ((size_t)b * LL + (size_t)c * LC) * DI + dq * 4;
    size_t zbase = ((size_t)b * LL + (size_t)c * LC) * (2 * DI) + DI + dq * 4;
    float4 Dd = *(const float4*)(Dvec + dq * 4);
    float4 st = ((const float4*)Cy)[gid];
    #pragma unroll 4
    for (int l = 0; l < LC; l++) {
        float4 et = *(const float4*)(e + base + (size_t)l * DI);
        float4 ut = load_half4(uh + base + (size_t)l * DI);
        float4 zt = *(const float4*)(xz + zbase + (size_t)l * (2 * DI));
        st.x = clip1e4(fmaf(st.x, et.x, ut.x));
        st.y = clip1e4(fmaf(st.y, et.y, ut.y));
        st.z = clip1e4(fmaf(st.z, et.z, ut.z));
        st.w = clip1e4(fmaf(st.w, et.w, ut.w));
        float4 o;
        o.x = clip1e4(fmaf(ut.x, Dd.x, st.x)) * (zt.x / (1.f + expf(-zt.x)));
        o.y = clip1e4(fmaf(ut.y, Dd.y, st.y)) * (zt.y / (1.f + expf(-zt.y)));
        o.z = clip1e4(fmaf(ut.z, Dd.z, st.z)) * (zt.z / (1.f + expf(-zt.z)));
        o.w = clip1e4(fmaf(ut.w, Dd.w, st.w)) * (zt.w / (1.f + expf(-zt.w)));
        store_half4(ygh + base + (size_t)l * DI, o);
    }
}

// ---------------------------------------------------------------------------
// Launch
// ---------------------------------------------------------------------------
extern "C" void kernel_launch(void* const* d_in, const int* in_sizes, int n_in,
                              void* d_out, int out_size) {
    const float* x     = (const float*)d_in[0];
    const float* inw   = (const float*)d_in[1];
    const float* convw = (const float*)d_in[2];
    const float* convb = (const float*)d_in[3];
    const float* xpw   = (const float*)d_in[4];
    const float* dtw   = (const float*)d_in[5];
    const float* dtb   = (const float*)d_in[6];
    const float* alog  = (const float*)d_in[7];
    const float* Dvec  = (const float*)d_in[8];
    const float* outw  = (const float*)d_in[9];
    float* out = (float*)d_out;

    float *xz, *e, *S, *P, *Cy;
    __half *uh, *dtlowh, *ygh, *xh, *inwh, *outwh, *xpwh, *dtwh;
    cudaGetSymbolAddress((void**)&xz, g_xz);
    cudaGetSymbolAddress((void**)&uh, g_uh);
    cudaGetSymbolAddress((void**)&dtlowh, g_dtlowh);
    cudaGetSymbolAddress((void**)&e, g_e);
    cudaGetSymbolAddress((void**)&ygh, g_ygh);
    cudaGetSymbolAddress((void**)&S, g_S);
    cudaGetSymbolAddress((void**)&P, g_P);
    cudaGetSymbolAddress((void**)&Cy, g_C);
    cudaGetSymbolAddress((void**)&xh, g_xh);
    cudaGetSymbolAddress((void**)&inwh, g_inwh);
    cudaGetSymbolAddress((void**)&outwh, g_outwh);
    cudaGetSymbolAddress((void**)&xpwh, g_xpwh);
    cudaGetSymbolAddress((void**)&dtwh, g_dtwh);

    const int SM128 = 2 * (128 * SSTH + 128 * SSTH) * 2;   // 73728 B (>= 128*EST*4)
    const int SM64  = 2 * (128 * SSTH + 64 * SSTH) * 2;    // 55296 B
    cudaFuncSetAttribute((const void*)gemm_f16<128, 0>,
                         cudaFuncAttributeMaxDynamicSharedMemorySize, SM128);
    cudaFuncSetAttribute((const void*)gemm_f16<128, 2>,
                         cudaFuncAttributeMaxDynamicSharedMemorySize, SM128);
    cudaFuncSetAttribute((const void*)gemm_f16<64, 3>,
                         cudaFuncAttributeMaxDynamicSharedMemorySize, SM64);

    // 0. f32 -> f16 conversion prepasses
    to_half_kernel<<<(ROWS * DMOD / 8 + 255) / 256, 256>>>(x, xh, ROWS * DMOD / 8);
    to_half_kernel<<<(2 * DI * DMOD / 8 + 255) / 256, 256>>>(inw, inwh, 2 * DI * DMOD / 8);
    to_half_kernel<<<(DMOD * DI / 8 + 255) / 256, 256>>>(outw, outwh, DMOD * DI / 8);
    to_half_kernel<<<(DTR * DI / 8 + 255) / 256, 256>>>(xpw, xpwh, DTR * DI / 8);
    to_half_kernel<<<(DI * DTR / 8 + 255) / 256, 256>>>(dtw, dtwh, DI * DTR / 8);

    // 1. in_proj: xz[8192,4096] = xh * inwh^T   (K=1024)
    gemm_f16<128, 0><<<dim3((2 * DI) / 128, ROWS / 128), 256, SM128>>>(
        xh, inwh, xz, nullptr, ROWS, 2 * DI, DMOD,
        nullptr, nullptr, nullptr, nullptr, nullptr);
    // 2. conv + silu -> uh (f16)
    conv_silu_kernel<<<(ROWS / 8) * (DI / 4) / 256, 256>>>(xz, convw, convb, uh);
    // 3. dtlow[8192,64] = uh * xpwh^T  (K=2048) -> half
    gemm_f16<64, 3><<<dim3(1, ROWS / 128), 256, SM64>>>(
        uh, xpwh, nullptr, dtlowh, ROWS, DTR, DI,
        nullptr, nullptr, nullptr, nullptr, nullptr);
    // 4. e = f(dtlowh * dtwh^T + dtb)  (K=64) + fused scan pass1 -> S, P
    gemm_f16<128, 2><<<dim3(DI / 128, ROWS / 128), 256, SM128>>>(
        dtlowh, dtwh, e, nullptr, ROWS, DI, DTR,
        dtb, alog, uh, S, P);
    // 5. carry + scan pass2
    carry_kernel<<<(BB * DI / 4) / 128, 128>>>(S, P, Cy);
    scan_pass2<<<(BB * NCH * DI / 4) / 256, 256>>>(e, uh, xz, Dvec, Cy, ygh);
    // 6. out_proj: out[8192,1024] = ygh * outwh^T  (K=2048)
    gemm_f16<128, 0><<<dim3(DMOD / 128, ROWS / 128), 256, SM128>>>(
        ygh, outwh, out, nullptr, ROWS, DMOD, DI,
        nullptr, nullptr, nullptr, nullptr, nullptr);
}

// round 8
// speedup vs baseline: 1.7848x; 1.0456x over previous
#include <cuda_runtime.h>
#include <cuda_fp16.h>
#include <math.h>
#include <stdint.h>

// ---------------------------------------------------------------------------
// Problem constants
// ---------------------------------------------------------------------------
#define BB 2
#define LL 4096
#define DMOD 1024
#define DI 2048
#define DTR 64
#define KC 4
#define ROWS (BB * LL)       // 8192
#define NCH 64               // scan chunks
#define LC (LL / NCH)        // 64
#define NSPLIT 4             // dtlow split-K factor
#define KSL (DI / NSPLIT)    // 512

// ---------------------------------------------------------------------------
// Scratch (device globals; no allocation allowed)
// ---------------------------------------------------------------------------
__device__ __half g_xzh[(size_t)ROWS * 2 * DI];    // in_proj out (xi | z), f16
__device__ __half g_uh[(size_t)ROWS * DI];         // conv+silu out f16
__device__ float  g_dtp[(size_t)NSPLIT * ROWS * DTR]; // dtlow split-K partials
__device__ __half g_dtlowh[(size_t)ROWS * DTR];    // dt_low f16
__device__ float  g_e [(size_t)ROWS * DI];         // decay factors f32
__device__ __half g_ygh[(size_t)ROWS * DI];        // gated scan out f16
__device__ float  g_S [(size_t)BB * NCH * DI];
__device__ float  g_P [(size_t)BB * NCH * DI];
__device__ float  g_C [(size_t)BB * NCH * DI];
// fp16 operand copies
__device__ __half g_xh  [(size_t)ROWS * DMOD];
__device__ __half g_inwh[(size_t)2 * DI * DMOD];
__device__ __half g_outwh[(size_t)DMOD * DI];
__device__ __half g_xpwh[(size_t)DTR * DI];
__device__ __half g_dtwh[(size_t)DI * DTR];

// ---------------------------------------------------------------------------
// PTX helpers (generic ISA: cp.async + ldmatrix + mma.sync f16 — sm_103-safe)
// ---------------------------------------------------------------------------
__device__ __forceinline__ uint32_t smem_u32(const void* p) {
    uint32_t a;
    asm("{ .reg .u64 t; cvta.to.shared.u64 t, %1; cvt.u32.u64 %0, t; }"
        : "=r"(a) : "l"(p));
    return a;
}
__device__ __forceinline__ void cp_async16(uint32_t dst, const void* src) {
    asm volatile("cp.async.cg.shared.global [%0], [%1], 16;"
                 :: "r"(dst), "l"(src) : "memory");
}
#define CP_COMMIT() asm volatile("cp.async.commit_group;" ::: "memory")
#define CP_WAIT(n)  asm volatile("cp.async.wait_group %0;" :: "n"(n) : "memory")

__device__ __forceinline__ void ldsm_x4(uint32_t* d, uint32_t addr) {
    asm volatile("ldmatrix.sync.aligned.m8n8.x4.shared.b16 {%0,%1,%2,%3}, [%4];"
                 : "=r"(d[0]), "=r"(d[1]), "=r"(d[2]), "=r"(d[3]) : "r"(addr));
}
__device__ __forceinline__ void mma_f16(float* c, const uint32_t* a, const uint32_t* b) {
    asm volatile(
        "mma.sync.aligned.m16n8k16.row.col.f32.f16.f16.f32 "
        "{%0,%1,%2,%3}, {%4,%5,%6,%7}, {%8,%9}, {%0,%1,%2,%3};"
        : "+f"(c[0]), "+f"(c[1]), "+f"(c[2]), "+f"(c[3])
        : "r"(a[0]), "r"(a[1]), "r"(a[2]), "r"(a[3]), "r"(b[0]), "r"(b[1]));
}

__device__ __forceinline__ float e_from_dpre(float acc, float bias, float al) {
    float v = acc + bias;
    float delta = (v > 20.f) ? v : log1pf(expf(v));
    delta = fminf(fmaxf(delta, 1e-6f), 10.f);
    float A = fminf(fmaxf(-expf(al), -10.f), -1e-6f);
    float ev = expf(delta * A);
    return fminf(fmaxf(ev, 1e-6f), 1.f);
}
__device__ __forceinline__ float clip1e4(float v) {
    return fminf(fmaxf(v, -1e4f), 1e4f);
}

// ---------------------------------------------------------------------------
// fp16 tensor-core GEMM: C[M,N] = A[M,K]*B[N,K]^T (A,B half row-major).
// BM=128, BN template. BK=64 halves. 256 threads, 8 warps (2x4).
// SSTH=72 halves (144B rows) -> conflict-free ldmatrix.
// Kst = row stride of A/B in K elements; Ksl = reduced-K length this launch.
// SPLITK: offset A/B by blockIdx.z*Ksl (cols) and C by blockIdx.z*M*N.
// EPI: 0 = f32 store
//      2 = fused e-epilogue + scan pass1 (vb1=dtb, vb2=A_log, U=uh -> Sp,Pp)
//      3 = half store to Ch.
// ---------------------------------------------------------------------------
#define SSTH 72
#define BKH  64
#define EST  132   // e-tile smem stride (floats)

template <int BN, int EPI, bool SPLITK>
__global__ __launch_bounds__(256, 2)
void gemm_f16(const __half* __restrict__ A, const __half* __restrict__ B,
              float* __restrict__ C, __half* __restrict__ Ch,
              int M, int N, int Kst, int Ksl,
              const float* __restrict__ vb1, const float* __restrict__ vb2,
              const __half* __restrict__ U,
              float* __restrict__ Sp, float* __restrict__ Pp) {
    constexpr int MT = 4;
    constexpr int NT = BN / 32;
    constexpr int NPAIR = NT / 2;
    constexpr int AF = (128 * 8) / 256;
    constexpr int BF = (BN * 8) / 256;

    extern __shared__ __half smem[];
    const uint32_t sA = smem_u32(smem);
    const uint32_t sB = sA + 2 * 128 * SSTH * 2;

    const int tid = threadIdx.x;
    const int wid = tid >> 5;
    const int lane = tid & 31;
    const int grp = lane >> 2;
    const int qid = lane & 3;
    const int wm = wid >> 2;
    const int wn = wid & 3;

    const int bx = blockIdx.x, by = blockIdx.y;
    const int K = Kst;
    const __half* Ag = A + (size_t)by * 128 * K;
    const __half* Bg = B + (size_t)bx * BN * K;
    if (SPLITK) {
        Ag += (size_t)blockIdx.z * Ksl;
        Bg += (size_t)blockIdx.z * Ksl;
        C  += (size_t)blockIdx.z * M * N;
    }

    const int a_row = lane & 15;
    const int a_kb  = (lane >> 4) * 16;
    const int b_row = ((lane >> 4) << 3) + (lane & 7);
    const int b_kb  = ((lane >> 3) & 1) * 16;

    float acc[MT][NT][4];
    #pragma unroll
    for (int i = 0; i < MT; i++)
        #pragma unroll
        for (int j = 0; j < NT; j++)
            #pragma unroll
            for (int q = 0; q < 4; q++) acc[i][j][q] = 0.f;

    const int nK = Ksl / BKH;

    #pragma unroll
    for (int t = 0; t < AF; t++) {
        int f = tid + t * 256;
        int row = f >> 3, c = f & 7;
        cp_async16(sA + row * 144 + c * 16, Ag + (size_t)row * K + c * 8);
    }
    #pragma unroll
    for (int t = 0; t < BF; t++) {
        int f = tid + t * 256;
        int row = f >> 3, c = f & 7;
        cp_async16(sB + row * 144 + c * 16, Bg + (size_t)row * K + c * 8);
    }
    CP_COMMIT();

    int buf = 0;
    for (int kt = 0; kt < nK; kt++) {
        if (kt + 1 < nK) {
            const uint32_t dA = sA + (buf ^ 1) * 128 * SSTH * 2;
            const uint32_t dB = sB + (buf ^ 1) * BN * SSTH * 2;
            const int koff = (kt + 1) * BKH;
            #pragma unroll
            for (int t = 0; t < AF; t++) {
                int f = tid + t * 256;
                int row = f >> 3, c = f & 7;
                cp_async16(dA + row * 144 + c * 16, Ag + (size_t)row * K + koff + c * 8);
            }
            #pragma unroll
            for (int t = 0; t < BF; t++) {
                int f = tid + t * 256;
                int row = f >> 3, c = f & 7;
                cp_async16(dB + row * 144 + c * 16, Bg + (size_t)row * K + koff + c * 8);
            }
            CP_COMMIT();
            CP_WAIT(1);
        } else {
            CP_WAIT(0);
        }
        __syncthreads();

        const uint32_t Ab = sA + buf * 128 * SSTH * 2;
        const uint32_t Bb = sB + buf * BN * SSTH * 2;

        uint32_t addrA[MT], addrB[NPAIR];
        #pragma unroll
        for (int mt = 0; mt < MT; mt++)
            addrA[mt] = Ab + (wm * 64 + mt * 16 + a_row) * 144 + a_kb;
        #pragma unroll
        for (int p = 0; p < NPAIR; p++)
            addrB[p] = Bb + (wn * (NT * 8) + p * 16 + b_row) * 144 + b_kb;

        #pragma unroll
        for (int s = 0; s < BKH / 16; s++) {
            uint32_t af[MT][4];
            #pragma unroll
            for (int mt = 0; mt < MT; mt++)
                ldsm_x4(af[mt], addrA[mt] + s * 32);
            uint32_t bf[NPAIR][4];
            #pragma unroll
            for (int p = 0; p < NPAIR; p++)
                ldsm_x4(bf[p], addrB[p] + s * 32);
            #pragma unroll
            for (int mt = 0; mt < MT; mt++)
                #pragma unroll
                for (int nt = 0; nt < NT; nt++)
                    mma_f16(acc[mt][nt], af[mt], &bf[nt >> 1][(nt & 1) * 2]);
        }
        __syncthreads();
        buf ^= 1;
    }

    float* se = (float*)smem;   // e-tile stash for EPI==2 (128 x EST)

    // epilogue
    #pragma unroll
    for (int mt = 0; mt < MT; mt++) {
        const int rl = wm * 64 + mt * 16 + grp;
        const int r0 = by * 128 + rl;
        #pragma unroll
        for (int nt = 0; nt < NT; nt++) {
            const int cl = wn * (NT * 8) + nt * 8 + qid * 2;
            const int c0 = bx * BN + cl;
            float o0 = acc[mt][nt][0], o1 = acc[mt][nt][1];
            float o2 = acc[mt][nt][2], o3 = acc[mt][nt][3];
            if (EPI == 2) {
                float2 bb = *(const float2*)(vb1 + c0);
                float2 aa = *(const float2*)(vb2 + c0);
                o0 = e_from_dpre(o0, bb.x, aa.x); o1 = e_from_dpre(o1, bb.y, aa.y);
                o2 = e_from_dpre(o2, bb.x, aa.x); o3 = e_from_dpre(o3, bb.y, aa.y);
                *(float2*)(se + rl * EST + cl) = make_float2(o0, o1);
                *(float2*)(se + (rl + 8) * EST + cl) = make_float2(o2, o3);
            }
            if (EPI == 3) {
                *(__half2*)(Ch + (size_t)r0 * N + c0) = __floats2half2_rn(o0, o1);
                *(__half2*)(Ch + (size_t)(r0 + 8) * N + c0) = __floats2half2_rn(o2, o3);
            } else {
                *(float2*)(C + (size_t)r0 * N + c0) = make_float2(o0, o1);
                *(float2*)(C + (size_t)(r0 + 8) * N + c0) = make_float2(o2, o3);
            }
        }
    }

    if (EPI == 2) {
        // fused scan pass1: 2 chunks x 128 d per block, one thread each.
        __syncthreads();
        const int ci = tid >> 7;
        const int dl = tid & 127;
        const size_t row0 = (size_t)by * 128 + ci * 64;
        const int b = (int)(row0 >> 12);
        const int c = (int)((row0 & 4095) >> 6);
        const int d = bx * BN + dl;
        const __half* up = U + row0 * N + d;
        const float* ep = se + ci * 64 * EST + dl;
        float st = 0.f, pr = 1.f;
        #pragma unroll 8
        for (int l = 0; l < LC; l++) {
            float et = ep[l * EST];
            float ut = __half2float(up[(size_t)l * N]);
            st = clip1e4(fmaf(st, et, ut));
            pr *= et;
        }
        const size_t gi = ((size_t)b * NCH + c) * DI + d;
        Sp[gi] = st;
        Pp[gi] = pr;
    }
}

// ---------------------------------------------------------------------------
// Batched f32 -> f16 conversion prepass (all 5 operands in one launch).
// ---------------------------------------------------------------------------
#define N8_X    (ROWS * DMOD / 8)            // 1048576
#define N8_INW  (2 * DI * DMOD / 8)          // 524288
#define N8_OUTW (DMOD * DI / 8)              // 262144
#define N8_XPW  (DTR * DI / 8)               // 16384
#define N8_DTW  (DI * DTR / 8)               // 16384
#define N8_TOT  (N8_X + N8_INW + N8_OUTW + N8_XPW + N8_DTW)

__device__ __forceinline__ void cvt8(const float* in, __half* out, int i) {
    float4 v0 = ((const float4*)in)[2 * i];
    float4 v1 = ((const float4*)in)[2 * i + 1];
    __half2 h0 = __floats2half2_rn(v0.x, v0.y);
    __half2 h1 = __floats2half2_rn(v0.z, v0.w);
    __half2 h2 = __floats2half2_rn(v1.x, v1.y);
    __half2 h3 = __floats2half2_rn(v1.z, v1.w);
    uint4 o;
    o.x = *(uint32_t*)&h0; o.y = *(uint32_t*)&h1;
    o.z = *(uint32_t*)&h2; o.w = *(uint32_t*)&h3;
    ((uint4*)out)[i] = o;
}

__global__ __launch_bounds__(256)
void prep_all_kernel(const float* x, __half* xh,
                     const float* inw, __half* inwh,
                     const float* outw, __half* outwh,
                     const float* xpw, __half* xpwh,
                     const float* dtw, __half* dtwh) {
    int i = blockIdx.x * blockDim.x + threadIdx.x;
    if (i < N8_X) { cvt8(x, xh, i); return; }
    i -= N8_X;
    if (i < N8_INW) { cvt8(inw, inwh, i); return; }
    i -= N8_INW;
    if (i < N8_OUTW) { cvt8(outw, outwh, i); return; }
    i -= N8_OUTW;
    if (i < N8_XPW) { cvt8(xpw, xpwh, i); return; }
    i -= N8_XPW;
    if (i < N8_DTW) cvt8(dtw, dtwh, i);
}

// ---------------------------------------------------------------------------
// dtlow split-K reduce: sum 4 f32 partials -> half.
// ---------------------------------------------------------------------------
__global__ __launch_bounds__(256)
void dtred_kernel(const float* __restrict__ dtp, __half* __restrict__ dtlowh) {
    int i = blockIdx.x * blockDim.x + threadIdx.x;     // < ROWS*DTR/4
    const int STRIDE4 = ROWS * DTR / 4;
    float4 a = ((const float4*)dtp)[i];
    float4 b = ((const float4*)dtp)[i + STRIDE4];
    float4 c = ((const float4*)dtp)[i + 2 * STRIDE4];
    float4 d = ((const float4*)dtp)[i + 3 * STRIDE4];
    float4 s = make_float4(a.x + b.x + c.x + d.x, a.y + b.y + c.y + d.y,
                           a.z + b.z + c.z + d.z, a.w + b.w + c.w + d.w);
    __half2 lo = __floats2half2_rn(s.x, s.y);
    __half2 hi = __floats2half2_rn(s.z, s.w);
    uint2 o; o.x = *(uint32_t*)&lo; o.y = *(uint32_t*)&hi;
    ((uint2*)dtlowh)[i] = o;
}

// ---------------------------------------------------------------------------
// half4 load/store helpers
// ---------------------------------------------------------------------------
__device__ __forceinline__ void store_half4(__half* p, float4 v) {
    __half2 lo = __floats2half2_rn(v.x, v.y);
    __half2 hi = __floats2half2_rn(v.z, v.w);
    uint2 o; o.x = *(uint32_t*)&lo; o.y = *(uint32_t*)&hi;
    *(uint2*)p = o;
}
__device__ __forceinline__ float4 load_half4(const __half* p) {
    uint2 v = *(const uint2*)p;
    float2 f0 = __half22float2(*(__half2*)&v.x);
    float2 f1 = __half22float2(*(__half2*)&v.y);
    return make_float4(f0.x, f0.y, f1.x, f1.y);
}
__device__ __forceinline__ float4 silu4(float4 a) {
    a.x = a.x / (1.f + expf(-a.x));
    a.y = a.y / (1.f + expf(-a.y));
    a.z = a.z / (1.f + expf(-a.z));
    a.w = a.w / (1.f + expf(-a.w));
    return a;
}
__device__ __forceinline__ float4 fma4(float4 a, float4 b, float4 c) {
    return make_float4(fmaf(a.x, b.x, c.x), fmaf(a.y, b.y, c.y),
                       fmaf(a.z, b.z, c.z), fmaf(a.w, b.w, c.w));
}

// ---------------------------------------------------------------------------
// Depthwise causal conv1d + bias + SiLU. half in, half out.
// ---------------------------------------------------------------------------
__global__ __launch_bounds__(256)
void conv_silu_kernel(const __half* __restrict__ xzh,
                      const float* __restrict__ cw,
                      const float* __restrict__ cb,
                      __half* __restrict__ uh) {
    int idx = blockIdx.x * blockDim.x + threadIdx.x;
    int dq = idx & (DI / 4 - 1);
    int g = idx >> 9;
    int l0 = (g & (LL / 8 - 1)) * 8;
    int b = g >> 9;
    size_t bl0 = (size_t)b * LL + l0;
    const int d = dq * 4;

    float4 r0 = *(const float4*)(cw + (d + 0) * KC);
    float4 r1 = *(const float4*)(cw + (d + 1) * KC);
    float4 r2 = *(const float4*)(cw + (d + 2) * KC);
    float4 r3 = *(const float4*)(cw + (d + 3) * KC);
    float4 w0 = make_float4(r0.x, r1.x, r2.x, r3.x);
    float4 w1 = make_float4(r0.y, r1.y, r2.y, r3.y);
    float4 w2 = make_float4(r0.z, r1.z, r2.z, r3.z);
    float4 w3 = make_float4(r0.w, r1.w, r2.w, r3.w);
    float4 bias = *(const float4*)(cb + d);

    float4 xm3 = make_float4(0, 0, 0, 0), xm2 = xm3, xm1 = xm3;
    if (l0 > 0) {
        xm3 = load_half4(xzh + (bl0 - 3) * (2 * DI) + d);
        xm2 = load_half4(xzh + (bl0 - 2) * (2 * DI) + d);
        xm1 = load_half4(xzh + (bl0 - 1) * (2 * DI) + d);
    }
    #pragma unroll
    for (int j = 0; j < 8; j++) {
        float4 xc = load_half4(xzh + (bl0 + j) * (2 * DI) + d);
        float4 acc = bias;
        acc = fma4(w0, xm3, acc);
        acc = fma4(w1, xm2, acc);
        acc = fma4(w2, xm1, acc);
        acc = fma4(w3, xc, acc);
        store_half4(uh + (bl0 + j) * DI + d, silu4(acc));
        xm3 = xm2; xm2 = xm1; xm1 = xc;
    }
}

// ---------------------------------------------------------------------------
// Carry + scan pass2
// ---------------------------------------------------------------------------
__global__ __launch_bounds__(128)
void carry_kernel(const float* __restrict__ S, const float* __restrict__ P,
                  float* __restrict__ Cy) {
    int gid = blockIdx.x * blockDim.x + threadIdx.x;
    int b = gid / (DI / 4);
    int dq = gid - b * (DI / 4);
    float4 cr = make_float4(0, 0, 0, 0);
    for (int c = 0; c < NCH; c++) {
        size_t i4 = ((size_t)b * NCH + c) * (DI / 4) + dq;
        ((float4*)Cy)[i4] = cr;
        float4 p = ((const float4*)P)[i4];
        float4 s = ((const float4*)S)[i4];
        cr.x = clip1e4(fmaf(cr.x, p.x, s.x));
        cr.y = clip1e4(fmaf(cr.y, p.y, s.y));
        cr.z = clip1e4(fmaf(cr.z, p.z, s.z));
        cr.w = clip1e4(fmaf(cr.w, p.w, s.w));
    }
}

__global__ __launch_bounds__(256)
void scan_pass2(const float* __restrict__ e, const __half* __restrict__ uh,
                const __half* __restrict__ xzh, const float* __restrict__ Dvec,
                const float* __restrict__ Cy, __half* __restrict__ ygh) {
    int gid = blockIdx.x * blockDim.x + threadIdx.x;
    int dq = gid & (DI / 4 - 1);
    int bc = gid / (DI / 4);
    int c = bc & (NCH - 1);
    int b = bc / NCH;
    size_t base  = ((size_t)b * LL + (size_t)c * LC) * DI + dq * 4;
    size_t zbase = ((size_t)b * LL + (size_t)c * LC) * (2 * DI) + DI + dq * 4;
    float4 Dd = *(const float4*)(Dvec + dq * 4);
    float4 st = ((const float4*)Cy)[gid];
    #pragma unroll 4
    for (int l = 0; l < LC; l++) {
        float4 et = *(const float4*)(e + base + (size_t)l * DI);
        float4 ut = load_half4(uh + base + (size_t)l * DI);
        float4 zt = load_half4(xzh + zbase + (size_t)l * (2 * DI));
        st.x = clip1e4(fmaf(st.x, et.x, ut.x));
        st.y = clip1e4(fmaf(st.y, et.y, ut.y));
        st.z = clip1e4(fmaf(st.z, et.z, ut.z));
        st.w = clip1e4(fmaf(st.w, et.w, ut.w));
        float4 o;
        o.x = clip1e4(fmaf(ut.x, Dd.x, st.x)) * (zt.x / (1.f + expf(-zt.x)));
        o.y = clip1e4(fmaf(ut.y, Dd.y, st.y)) * (zt.y / (1.f + expf(-zt.y)));
        o.z = clip1e4(fmaf(ut.z, Dd.z, st.z)) * (zt.z / (1.f + expf(-zt.z)));
        o.w = clip1e4(fmaf(ut.w, Dd.w, st.w)) * (zt.w / (1.f + expf(-zt.w)));
        store_half4(ygh + base + (size_t)l * DI, o);
    }
}

// ---------------------------------------------------------------------------
// Launch
// ---------------------------------------------------------------------------
extern "C" void kernel_launch(void* const* d_in, const int* in_sizes, int n_in,
                              void* d_out, int out_size) {
    const float* x     = (const float*)d_in[0];
    const float* inw   = (const float*)d_in[1];
    const float* convw = (const float*)d_in[2];
    const float* convb = (const float*)d_in[3];
    const float* xpw   = (const float*)d_in[4];
    const float* dtw   = (const float*)d_in[5];
    const float* dtb   = (const float*)d_in[6];
    const float* alog  = (const float*)d_in[7];
    const float* Dvec  = (const float*)d_in[8];
    const float* outw  = (const float*)d_in[9];
    float* out = (float*)d_out;

    float *e, *S, *P, *Cy, *dtp;
    __half *xzh, *uh, *dtlowh, *ygh, *xh, *inwh, *outwh, *xpwh, *dtwh;
    cudaGetSymbolAddress((void**)&xzh, g_xzh);
    cudaGetSymbolAddress((void**)&uh, g_uh);
    cudaGetSymbolAddress((void**)&dtp, g_dtp);
    cudaGetSymbolAddress((void**)&dtlowh, g_dtlowh);
    cudaGetSymbolAddress((void**)&e, g_e);
    cudaGetSymbolAddress((void**)&ygh, g_ygh);
    cudaGetSymbolAddress((void**)&S, g_S);
    cudaGetSymbolAddress((void**)&P, g_P);
    cudaGetSymbolAddress((void**)&Cy, g_C);
    cudaGetSymbolAddress((void**)&xh, g_xh);
    cudaGetSymbolAddress((void**)&inwh, g_inwh);
    cudaGetSymbolAddress((void**)&outwh, g_outwh);
    cudaGetSymbolAddress((void**)&xpwh, g_xpwh);
    cudaGetSymbolAddress((void**)&dtwh, g_dtwh);

    const int SM128 = 2 * (128 * SSTH + 128 * SSTH) * 2;   // 73728 B
    const int SM64  = 2 * (128 * SSTH + 64 * SSTH) * 2;    // 55296 B
    cudaFuncSetAttribute((const void*)gemm_f16<128, 0, false>,
                         cudaFuncAttributeMaxDynamicSharedMemorySize, SM128);
    cudaFuncSetAttribute((const void*)gemm_f16<128, 2, false>,
                         cudaFuncAttributeMaxDynamicSharedMemorySize, SM128);
    cudaFuncSetAttribute((const void*)gemm_f16<128, 3, false>,
                         cudaFuncAttributeMaxDynamicSharedMemorySize, SM128);
    cudaFuncSetAttribute((const void*)gemm_f16<64, 0, true>,
                         cudaFuncAttributeMaxDynamicSharedMemorySize, SM64);

    // 0. batched f32 -> f16 conversion prepass
    prep_all_kernel<<<(N8_TOT + 255) / 256, 256>>>(
        x, xh, inw, inwh, outw, outwh, xpw, xpwh, dtw, dtwh);

    // 1. in_proj: xzh[8192,4096] = xh * inwh^T (K=1024), half output
    gemm_f16<128, 3, false><<<dim3((2 * DI) / 128, ROWS / 128), 256, SM128>>>(
        xh, inwh, nullptr, xzh, ROWS, 2 * DI, DMOD, DMOD,
        nullptr, nullptr, nullptr, nullptr, nullptr);
    // 2. conv + silu -> uh
    conv_silu_kernel<<<(ROWS / 8) * (DI / 4) / 256, 256>>>(xzh, convw, convb, uh);
    // 3. dtlow split-K: partials[4][8192,64] = uh * xpwh^T (K-slices of 512)
    gemm_f16<64, 0, true><<<dim3(1, ROWS / 128, NSPLIT), 256, SM64>>>(
        uh, xpwh, dtp, nullptr, ROWS, DTR, DI, KSL,
        nullptr, nullptr, nullptr, nullptr, nullptr);
    dtred_kernel<<<(ROWS * DTR / 4) / 256, 256>>>(dtp, dtlowh);
    // 4. e = f(dtlowh * dtwh^T + dtb) (K=64) + fused scan pass1 -> S, P
    gemm_f16<128, 2, false><<<dim3(DI / 128, ROWS / 128), 256, SM128>>>(
        dtlowh, dtwh, e, nullptr, ROWS, DI, DTR, DTR,
        dtb, alog, uh, S, P);
    // 5. carry + scan pass2
    carry_kernel<<<(BB * DI / 4) / 128, 128>>>(S, P, Cy);
    scan_pass2<<<(BB * NCH * DI / 4) / 256, 256>>>(e, uh, xzh, Dvec, Cy, ygh);
    // 6. out_proj: out[8192,1024] = ygh * outwh^T (K=2048), f32 output
    gemm_f16<128, 0, false><<<dim3(DMOD / 128, ROWS / 128), 256, SM128>>>(
        ygh, outwh, out, nullptr, ROWS, DMOD, DI, DI,
        nullptr, nullptr, nullptr, nullptr, nullptr);
}